// round 1
// baseline (speedup 1.0000x reference)
#include <cuda_runtime.h>

// ---------------------------------------------------------------------------
// LinearAttention collapse:
//   S_b   = X_b X_b^T                                  (64x64 Gram, pass A)
//   M_b   = (scale/4096) * sum_h Wout_h (Wk_h S_b Wv_h^T)^T Wq_h   (pass B)
//   y     = M_b x + b_out  ->  channel LayerNorm * g   (pass C)
// ---------------------------------------------------------------------------

#define N_TOK   262144            // 64*64*64 tokens per batch
#define NCH     64
#define TILES_A 8                 // 64-token tiles per gram block
#define TILES_C 4                 // 64-token tiles per apply block
#define PAD_A   68                // token-major row pad (16B-aligned rows)

__device__ float g_S [2 * 64 * 64];
__device__ float g_Mt[2 * 64 * 64];   // M transposed: [c][o], o contiguous

// ---- f32x2 packed-FMA helpers (FFMA2: only reachable via PTX) -------------
static __device__ __forceinline__ unsigned long long dup2(float v) {
    unsigned long long r;
    asm("mov.b64 %0,{%1,%1};" : "=l"(r) : "f"(v));
    return r;
}
static __device__ __forceinline__ void fma2(unsigned long long& d,
                                            unsigned long long a,
                                            unsigned long long b) {
    asm("fma.rn.f32x2 %0, %1, %2, %0;" : "+l"(d) : "l"(a), "l"(b));
}
static __device__ __forceinline__ void unpk(unsigned long long v, float& lo, float& hi) {
    asm("mov.b64 {%0,%1},%2;" : "=f"(lo), "=f"(hi) : "l"(v));
}

// ---------------------------------------------------------------------------
// Zero the accumulators (graph replays must be self-contained)
// ---------------------------------------------------------------------------
__global__ void zero_kernel() {
    int i = blockIdx.x * 256 + threadIdx.x;
    if (i < 2 * 64 * 64) {
        g_S[i]  = 0.0f;
        g_Mt[i] = 0.0f;
    }
}

// ---------------------------------------------------------------------------
// Pass A: S_b += X_b X_b^T over this block's 512 tokens.
// smem tile is token-major [t][PAD_A] so both operand reads are contiguous
// LDS.128. Thread (i,j) owns S rows 4i..4i+3, cols 4j..4j+3 (f32x2 col pairs).
// ---------------------------------------------------------------------------
__global__ void __launch_bounds__(256) gram_kernel(const float* __restrict__ x) {
    __shared__ float sx[64 * PAD_A];
    const int b   = blockIdx.y;
    const float* xb = x + (size_t)b * NCH * N_TOK;
    const int tid = threadIdx.x;
    const int i   = tid & 15;
    const int j   = tid >> 4;

    unsigned long long acc[4][2];
#pragma unroll
    for (int r = 0; r < 4; r++) { acc[r][0] = 0ull; acc[r][1] = 0ull; }

    const int tok0 = blockIdx.x * (TILES_A * 64);
    for (int tile = 0; tile < TILES_A; tile++) {
        const int base = tok0 + tile * 64;
        // load 64ch x 64tok, transposing to token-major
#pragma unroll
        for (int k = 0; k < 4; k++) {
            int idx = k * 256 + tid;
            int c   = idx >> 4;
            int t4  = (idx & 15) << 2;
            float4 v = *reinterpret_cast<const float4*>(xb + (size_t)c * N_TOK + base + t4);
            sx[(t4 + 0) * PAD_A + c] = v.x;
            sx[(t4 + 1) * PAD_A + c] = v.y;
            sx[(t4 + 2) * PAD_A + c] = v.z;
            sx[(t4 + 3) * PAD_A + c] = v.w;
        }
        __syncthreads();
#pragma unroll 8
        for (int t = 0; t < 64; t++) {
            const float* row = &sx[t * PAD_A];
            float4 a4        = *reinterpret_cast<const float4*>(row + 4 * i);
            ulonglong2 b2    = *reinterpret_cast<const ulonglong2*>(row + 4 * j);
            unsigned long long d0 = dup2(a4.x), d1 = dup2(a4.y);
            unsigned long long d2 = dup2(a4.z), d3 = dup2(a4.w);
            fma2(acc[0][0], d0, b2.x); fma2(acc[0][1], d0, b2.y);
            fma2(acc[1][0], d1, b2.x); fma2(acc[1][1], d1, b2.y);
            fma2(acc[2][0], d2, b2.x); fma2(acc[2][1], d2, b2.y);
            fma2(acc[3][0], d3, b2.x); fma2(acc[3][1], d3, b2.y);
        }
        __syncthreads();
    }

    float* Sb = g_S + b * 4096;
#pragma unroll
    for (int r = 0; r < 4; r++) {
#pragma unroll
        for (int cp = 0; cp < 2; cp++) {
            float lo, hi;
            unpk(acc[r][cp], lo, hi);
            atomicAdd(&Sb[(4 * i + r) * 64 + 4 * j + 2 * cp + 0], lo);
            atomicAdd(&Sb[(4 * i + r) * 64 + 4 * j + 2 * cp + 1], hi);
        }
    }
}

// ---------------------------------------------------------------------------
// Pass B: fold weights. One block per (head, batch); atomicAdd into g_Mt.
//   A1 = Wk_h S ; C = coef * A1 Wv_h^T ; P = C^T Wq_h ; Mc = Wout_h P
// ---------------------------------------------------------------------------
__global__ void __launch_bounds__(256) combine_kernel(const float* __restrict__ w_qkv,
                                                      const float* __restrict__ w_out) {
    __shared__ float sS[4096];
    __shared__ float sA[2048];
    __shared__ float sC[1024];
    __shared__ float sP[2048];
    const int b = blockIdx.y, h = blockIdx.x;
    const int tid = threadIdx.x;

    const float* Sb = g_S + b * 4096;
    for (int k = tid; k < 4096; k += 256) sS[k] = Sb[k];
    __syncthreads();

    const float* Wq = w_qkv + (h * 32) * 64;
    const float* Wk = w_qkv + (128 + h * 32) * 64;
    const float* Wv = w_qkv + (256 + h * 32) * 64;

    // A1[i][c] = sum_c2 Wk[i][c2] * S[c2][c]
    for (int e = tid; e < 2048; e += 256) {
        int ii = e >> 6, c = e & 63;
        float s = 0.0f;
        for (int c2 = 0; c2 < 64; c2++) s += Wk[ii * 64 + c2] * sS[c2 * 64 + c];
        sA[e] = s;
    }
    __syncthreads();

    const float coef = 0.17677669529663688f / 4096.0f;  // 32^-0.5 / (H*W)
    // C[i][j] = coef * sum_c A1[i][c] * Wv[j][c]
    for (int e = tid; e < 1024; e += 256) {
        int ii = e >> 5, jj = e & 31;
        float s = 0.0f;
        for (int c = 0; c < 64; c++) s += sA[ii * 64 + c] * Wv[jj * 64 + c];
        sC[e] = s * coef;
    }
    __syncthreads();

    // P[j][c] = sum_i C[i][j] * Wq[i][c]
    for (int e = tid; e < 2048; e += 256) {
        int jj = e >> 6, c = e & 63;
        float s = 0.0f;
        for (int ii = 0; ii < 32; ii++) s += sC[ii * 32 + jj] * Wq[ii * 64 + c];
        sP[e] = s;
    }
    __syncthreads();

    // Mc[o][c] = sum_j Wout[o][h*32+j] * P[j][c]  -> accumulate transposed
    float* Mtb = g_Mt + b * 4096;
    for (int e = tid; e < 4096; e += 256) {
        int o = e >> 6, c = e & 63;
        float s = 0.0f;
        for (int jj = 0; jj < 32; jj++) s += w_out[o * 128 + h * 32 + jj] * sP[jj * 64 + c];
        atomicAdd(&Mtb[c * 64 + o], s);
    }
}

// ---------------------------------------------------------------------------
// Pass C: y = M x + b_out, then channel LayerNorm * g.
// Thread (og,tg) owns a 4(o) x 4(t) patch; o pairs packed in f32x2 lanes.
// Per-token mean/var via 16-lane shfl butterfly (no smem y round-trip).
// ---------------------------------------------------------------------------
__global__ void __launch_bounds__(256) apply_kernel(const float* __restrict__ x,
                                                    const float* __restrict__ b_out,
                                                    const float* __restrict__ gain,
                                                    float* __restrict__ out) {
    __shared__ float sM[4096];  // Mt: [c][o], o contiguous
    __shared__ float sX[4096];  // [c][t], t contiguous
    const int b   = blockIdx.y;
    const int tid = threadIdx.x;
    const float* xb  = x + (size_t)b * NCH * N_TOK;
    float*       ob  = out + (size_t)b * NCH * N_TOK;
    const float* Mtb = g_Mt + b * 4096;

#pragma unroll
    for (int k = 0; k < 4; k++) {
        int idx = k * 256 + tid;
        reinterpret_cast<float4*>(sM)[idx] = reinterpret_cast<const float4*>(Mtb)[idx];
    }

    const int og = tid & 15;   // o group: channels 4*og .. 4*og+3
    const int tg = tid >> 4;   // t group: tokens  4*tg .. 4*tg+3
    float bias[4], gq[4];
#pragma unroll
    for (int r = 0; r < 4; r++) {
        bias[r] = b_out[4 * og + r];
        gq[r]   = gain[4 * og + r];
    }

    const int tok0 = blockIdx.x * (TILES_C * 64);
    for (int tile = 0; tile < TILES_C; tile++) {
        const int base = tok0 + tile * 64;
        __syncthreads();  // sM ready (1st iter) / sX readers done (later iters)
#pragma unroll
        for (int k = 0; k < 4; k++) {
            int idx = k * 256 + tid;
            int c   = idx >> 4;
            int t4  = (idx & 15) << 2;
            *reinterpret_cast<float4*>(&sX[c * 64 + t4]) =
                *reinterpret_cast<const float4*>(xb + (size_t)c * N_TOK + base + t4);
        }
        __syncthreads();

        unsigned long long acc[2][4];
#pragma unroll
        for (int p = 0; p < 2; p++)
#pragma unroll
            for (int t = 0; t < 4; t++) acc[p][t] = 0ull;

#pragma unroll 8
        for (int c = 0; c < 64; c++) {
            ulonglong2 a2 = *reinterpret_cast<const ulonglong2*>(&sM[c * 64 + 4 * og]);
            float4 xv     = *reinterpret_cast<const float4*>(&sX[c * 64 + 4 * tg]);
            unsigned long long x0 = dup2(xv.x), x1 = dup2(xv.y);
            unsigned long long x2 = dup2(xv.z), x3 = dup2(xv.w);
            fma2(acc[0][0], a2.x, x0); fma2(acc[0][1], a2.x, x1);
            fma2(acc[0][2], a2.x, x2); fma2(acc[0][3], a2.x, x3);
            fma2(acc[1][0], a2.y, x0); fma2(acc[1][1], a2.y, x1);
            fma2(acc[1][2], a2.y, x2); fma2(acc[1][3], a2.y, x3);
        }

        // unpack: y[r][dt] for channel 4*og+r, token base+4*tg+dt (+ bias)
        float y[4][4];
#pragma unroll
        for (int p = 0; p < 2; p++)
#pragma unroll
            for (int t = 0; t < 4; t++) {
                float lo, hi;
                unpk(acc[p][t], lo, hi);
                y[2 * p + 0][t] = lo + bias[2 * p + 0];
                y[2 * p + 1][t] = hi + bias[2 * p + 1];
            }

        // per-token stats: the 16 og-lanes of a half-warp cover all 64 channels
        float ps[4], pq[4];
#pragma unroll
        for (int t = 0; t < 4; t++) {
            ps[t] = y[0][t] + y[1][t] + y[2][t] + y[3][t];
            pq[t] = y[0][t] * y[0][t] + y[1][t] * y[1][t] +
                    y[2][t] * y[2][t] + y[3][t] * y[3][t];
        }
#pragma unroll
        for (int m = 1; m < 16; m <<= 1) {
#pragma unroll
            for (int t = 0; t < 4; t++) {
                ps[t] += __shfl_xor_sync(0xffffffffu, ps[t], m);
                pq[t] += __shfl_xor_sync(0xffffffffu, pq[t], m);
            }
        }
        float meanv[4], istd[4];
#pragma unroll
        for (int t = 0; t < 4; t++) {
            meanv[t]  = ps[t] * (1.0f / 64.0f);
            float var = pq[t] * (1.0f / 64.0f) - meanv[t] * meanv[t];
            istd[t]   = rsqrtf(var + 1e-5f);
        }

        // normalize + store (4 tokens contiguous per channel -> STG.128)
#pragma unroll
        for (int r = 0; r < 4; r++) {
            float4 v;
            v.x = (y[r][0] - meanv[0]) * istd[0] * gq[r];
            v.y = (y[r][1] - meanv[1]) * istd[1] * gq[r];
            v.z = (y[r][2] - meanv[2]) * istd[2] * gq[r];
            v.w = (y[r][3] - meanv[3]) * istd[3] * gq[r];
            *reinterpret_cast<float4*>(ob + (size_t)(4 * og + r) * N_TOK + base + 4 * tg) = v;
        }
    }
}

// ---------------------------------------------------------------------------
extern "C" void kernel_launch(void* const* d_in, const int* in_sizes, int n_in,
                              void* d_out, int out_size) {
    const float* x     = (const float*)d_in[0];
    const float* w_qkv = (const float*)d_in[1];
    const float* w_out = (const float*)d_in[2];
    const float* b_out = (const float*)d_in[3];
    const float* g     = (const float*)d_in[4];
    float* out = (float*)d_out;

    zero_kernel<<<32, 256>>>();
    gram_kernel<<<dim3(N_TOK / (TILES_A * 64), 2), 256>>>(x);
    combine_kernel<<<dim3(4, 2), 256>>>(w_qkv, w_out);
    apply_kernel<<<dim3(N_TOK / (TILES_C * 64), 2), 256>>>(x, b_out, g, out);
}

// round 2
// speedup vs baseline: 1.0196x; 1.0196x over previous
#include <cuda_runtime.h>

#define N_TOK 262144            // 64*64*64 tokens per batch
#define NCH   64

__device__ float g_S [2 * 4096];
__device__ float g_Mt[2 * 4096];   // M transposed: [c][o], o contiguous

// ---- f32x2 packed helpers (only reachable via PTX) ------------------------
static __device__ __forceinline__ unsigned long long dup2(float v) {
    unsigned long long r;
    asm("mov.b64 %0,{%1,%1};" : "=l"(r) : "f"(v));
    return r;
}
static __device__ __forceinline__ unsigned long long pk2(float lo, float hi) {
    unsigned long long r;
    asm("mov.b64 %0,{%1,%2};" : "=l"(r) : "f"(lo), "f"(hi));
    return r;
}
static __device__ __forceinline__ void fma2(unsigned long long& d,
                                            unsigned long long a,
                                            unsigned long long b) {
    asm("fma.rn.f32x2 %0, %1, %2, %0;" : "+l"(d) : "l"(a), "l"(b));
}
static __device__ __forceinline__ unsigned long long add2(unsigned long long a,
                                                          unsigned long long b) {
    unsigned long long d;
    asm("add.rn.f32x2 %0,%1,%2;" : "=l"(d) : "l"(a), "l"(b));
    return d;
}
static __device__ __forceinline__ unsigned long long mul2(unsigned long long a,
                                                          unsigned long long b) {
    unsigned long long d;
    asm("mul.rn.f32x2 %0,%1,%2;" : "=l"(d) : "l"(a), "l"(b));
    return d;
}
static __device__ __forceinline__ void unpk(unsigned long long v, float& lo, float& hi) {
    asm("mov.b64 {%0,%1},%2;" : "=f"(lo), "=f"(hi) : "l"(v));
}

// ---------------------------------------------------------------------------
__global__ void zero_kernel() {
    int i = blockIdx.x * 256 + threadIdx.x;
    if (i < 2 * 4096) {
        g_S[i]  = 0.0f;
        g_Mt[i] = 0.0f;
    }
}

// ---------------------------------------------------------------------------
// Pass A: S_b = X_b X_b^T. Persistent blocks (148 per batch).
// 8x8 patch per thread, tokens split 4 ways (s), block-level smem reduction,
// one atomicAdd per element per block.
// smem: sx[64*68] (token-major tile) + sred[4][64*66]
// ---------------------------------------------------------------------------
#define GRAM_SMEM ((4352 + 4 * 4224) * 4)   // 84992 bytes

__global__ void __launch_bounds__(256, 2) gram_kernel(const float* __restrict__ x) {
    extern __shared__ float sm[];
    float* sx   = sm;          // 64 rows * 68 pad
    float* sred = sm + 4352;   // 4 copies * 64 rows * 66 pad

    const int b   = blockIdx.y;
    const float* xb = x + (size_t)b * NCH * N_TOK;
    const int tid = threadIdx.x;
    const int pi  = tid & 7;
    const int pj  = (tid >> 3) & 7;
    const int s   = tid >> 6;

    unsigned long long acc[8][4];
#pragma unroll
    for (int i = 0; i < 8; i++)
#pragma unroll
        for (int jp = 0; jp < 4; jp++) acc[i][jp] = 0ull;

    for (int tile = blockIdx.x; tile < N_TOK / 64; tile += 148) {
        const int base = tile * 64;
        __syncthreads();
        // load 64ch x 64tok, transpose to token-major
#pragma unroll
        for (int k = 0; k < 4; k++) {
            int idx = k * 256 + tid;
            int c   = idx >> 4;
            int t4  = (idx & 15) << 2;
            float4 v = *reinterpret_cast<const float4*>(xb + (size_t)c * N_TOK + base + t4);
            sx[(t4 + 0) * 68 + c] = v.x;
            sx[(t4 + 1) * 68 + c] = v.y;
            sx[(t4 + 2) * 68 + c] = v.z;
            sx[(t4 + 3) * 68 + c] = v.w;
        }
        __syncthreads();
#pragma unroll 4
        for (int tt = 0; tt < 16; tt++) {
            const float* row = &sx[(4 * tt + s) * 68];
            float4 a0     = *reinterpret_cast<const float4*>(row + 8 * pi);
            float4 a1     = *reinterpret_cast<const float4*>(row + 8 * pi + 4);
            ulonglong2 b0 = *reinterpret_cast<const ulonglong2*>(row + 8 * pj);
            ulonglong2 b1 = *reinterpret_cast<const ulonglong2*>(row + 8 * pj + 4);
            unsigned long long d0 = dup2(a0.x), d1 = dup2(a0.y);
            unsigned long long d2 = dup2(a0.z), d3 = dup2(a0.w);
            unsigned long long d4 = dup2(a1.x), d5 = dup2(a1.y);
            unsigned long long d6 = dup2(a1.z), d7 = dup2(a1.w);
            fma2(acc[0][0], d0, b0.x); fma2(acc[0][1], d0, b0.y);
            fma2(acc[0][2], d0, b1.x); fma2(acc[0][3], d0, b1.y);
            fma2(acc[1][0], d1, b0.x); fma2(acc[1][1], d1, b0.y);
            fma2(acc[1][2], d1, b1.x); fma2(acc[1][3], d1, b1.y);
            fma2(acc[2][0], d2, b0.x); fma2(acc[2][1], d2, b0.y);
            fma2(acc[2][2], d2, b1.x); fma2(acc[2][3], d2, b1.y);
            fma2(acc[3][0], d3, b0.x); fma2(acc[3][1], d3, b0.y);
            fma2(acc[3][2], d3, b1.x); fma2(acc[3][3], d3, b1.y);
            fma2(acc[4][0], d4, b0.x); fma2(acc[4][1], d4, b0.y);
            fma2(acc[4][2], d4, b1.x); fma2(acc[4][3], d4, b1.y);
            fma2(acc[5][0], d5, b0.x); fma2(acc[5][1], d5, b0.y);
            fma2(acc[5][2], d5, b1.x); fma2(acc[5][3], d5, b1.y);
            fma2(acc[6][0], d6, b0.x); fma2(acc[6][1], d6, b0.y);
            fma2(acc[6][2], d6, b1.x); fma2(acc[6][3], d6, b1.y);
            fma2(acc[7][0], d7, b0.x); fma2(acc[7][1], d7, b0.y);
            fma2(acc[7][2], d7, b1.x); fma2(acc[7][3], d7, b1.y);
        }
    }

    // stage 1: each s-group writes its private padded copy (no conflicts >2-way)
    __syncthreads();
    float* red = sred + s * 4224;
#pragma unroll
    for (int i = 0; i < 8; i++)
#pragma unroll
        for (int jp = 0; jp < 4; jp++)
            *reinterpret_cast<unsigned long long*>(
                &red[(8 * pi + i) * 66 + 8 * pj + 2 * jp]) = acc[i][jp];
    __syncthreads();

    // stage 2: sum 4 copies, one global atomic per element
    float* Sb = g_S + b * 4096;
#pragma unroll
    for (int k = 0; k < 16; k++) {
        int e = k * 256 + tid;
        int r = e >> 6, c = e & 63;
        float v = sred[r * 66 + c] + sred[4224 + r * 66 + c] +
                  sred[2 * 4224 + r * 66 + c] + sred[3 * 4224 + r * 66 + c];
        atomicAdd(&Sb[e], v);
    }
}

// ---------------------------------------------------------------------------
// Pass B: fold weights into M (transposed). One block per (head, batch).
// ---------------------------------------------------------------------------
__global__ void __launch_bounds__(256) combine_kernel(const float* __restrict__ w_qkv,
                                                      const float* __restrict__ w_out) {
    __shared__ float sS[4096];
    __shared__ float sA[2048];
    __shared__ float sC[1024];
    __shared__ float sP[2048];
    const int b = blockIdx.y, h = blockIdx.x;
    const int tid = threadIdx.x;

    const float* Sb = g_S + b * 4096;
    for (int k = tid; k < 4096; k += 256) sS[k] = Sb[k];
    __syncthreads();

    const float* Wq = w_qkv + (h * 32) * 64;
    const float* Wk = w_qkv + (128 + h * 32) * 64;
    const float* Wv = w_qkv + (256 + h * 32) * 64;

    for (int e = tid; e < 2048; e += 256) {
        int ii = e >> 6, c = e & 63;
        float s = 0.0f;
        for (int c2 = 0; c2 < 64; c2++) s += Wk[ii * 64 + c2] * sS[c2 * 64 + c];
        sA[e] = s;
    }
    __syncthreads();

    const float coef = 0.17677669529663688f / 4096.0f;  // 32^-0.5 / (H*W)
    for (int e = tid; e < 1024; e += 256) {
        int ii = e >> 5, jj = e & 31;
        float s = 0.0f;
        for (int c = 0; c < 64; c++) s += sA[ii * 64 + c] * Wv[jj * 64 + c];
        sC[e] = s * coef;
    }
    __syncthreads();

    for (int e = tid; e < 2048; e += 256) {
        int jj = e >> 6, c = e & 63;
        float s = 0.0f;
        for (int ii = 0; ii < 32; ii++) s += sC[ii * 32 + jj] * Wq[ii * 64 + c];
        sP[e] = s;
    }
    __syncthreads();

    float* Mtb = g_Mt + b * 4096;
    for (int e = tid; e < 4096; e += 256) {
        int o = e >> 6, c = e & 63;
        float s = 0.0f;
        for (int jj = 0; jj < 32; jj++) s += w_out[o * 128 + h * 32 + jj] * sP[jj * 64 + c];
        atomicAdd(&Mtb[c * 64 + o], s);
    }
}

// ---------------------------------------------------------------------------
// Pass C: y = M x + b_out, channel LayerNorm * gain.
// Persistent blocks. f32x2 packs TOKEN pairs (x loads pre-packed, zero MOVs);
// M pre-duplicated in smem, chunk-interleaved [c][j][og] for conflict-free LDS.
// Thread (og,tg) owns channels 8og..8og+7 x tokens 8tg..8tg+7.
// smem: sMd[64*128] + sX[64*256]
// ---------------------------------------------------------------------------
#define APPLY_SMEM ((8192 + 16384) * 4)   // 98304 bytes

__global__ void __launch_bounds__(256, 2) apply_kernel(const float* __restrict__ x,
                                                       const float* __restrict__ b_out,
                                                       const float* __restrict__ gain,
                                                       float* __restrict__ out) {
    extern __shared__ float sm[];
    float* sMd = sm;          // [c][j][og][dup-pair]  (64 * 128 floats)
    float* sX  = sm + 8192;   // [c][t]  (64 * 256 floats)

    const int b   = blockIdx.y;
    const int tid = threadIdx.x;
    const float* xb = x + (size_t)b * NCH * N_TOK;
    float*       ob = out + (size_t)b * NCH * N_TOK;
    const float* Mtb = g_Mt + b * 4096;

    // build duplicated, chunk-interleaved M
#pragma unroll
    for (int k = 0; k < 4; k++) {
        int idx = k * 256 + tid;          // float4 index into Mt
        int c   = idx >> 4;
        int a   = idx & 15;               // channels 4a..4a+3
        float4 v = reinterpret_cast<const float4*>(Mtb)[idx];
        int ogw = a >> 1;
        int j0  = (a & 1) * 2;
        float4 w0 = {v.x, v.x, v.y, v.y};
        float4 w1 = {v.z, v.z, v.w, v.w};
        *reinterpret_cast<float4*>(&sMd[c * 128 + j0 * 32 + ogw * 4])       = w0;
        *reinterpret_cast<float4*>(&sMd[c * 128 + (j0 + 1) * 32 + ogw * 4]) = w1;
    }

    const int og = tid & 7;    // channels 8*og..8*og+7
    const int tg = tid >> 3;   // tokens  8*tg..8*tg+7 within tile

    for (int tile = blockIdx.x; tile < N_TOK / 256; tile += 148) {
        const int base = tile * 256;
        __syncthreads();   // sMd ready (1st iter) / sX readers done (later)
#pragma unroll
        for (int k = 0; k < 16; k++) {
            int idx = k * 256 + tid;       // float4 index into tile
            int c   = idx >> 6;
            int t4  = (idx & 63) << 2;
            *reinterpret_cast<float4*>(&sX[c * 256 + t4]) =
                *reinterpret_cast<const float4*>(xb + (size_t)c * N_TOK + base + t4);
        }
        __syncthreads();

        // acc[o][tp] : channel 8og+o, token pair 2tp within this thread's 8 tokens
        unsigned long long acc[8][4];
        {
            float4 bv0 = *reinterpret_cast<const float4*>(b_out + 8 * og);
            float4 bv1 = *reinterpret_cast<const float4*>(b_out + 8 * og + 4);
            float bb[8] = {bv0.x, bv0.y, bv0.z, bv0.w, bv1.x, bv1.y, bv1.z, bv1.w};
#pragma unroll
            for (int o = 0; o < 8; o++) {
                unsigned long long d = dup2(bb[o]);
#pragma unroll
                for (int tp = 0; tp < 4; tp++) acc[o][tp] = d;
            }
        }

#pragma unroll 4
        for (int c = 0; c < 64; c++) {
            const float* mrow = &sMd[c * 128 + og * 4];
            ulonglong2 m0 = *reinterpret_cast<const ulonglong2*>(mrow);
            ulonglong2 m1 = *reinterpret_cast<const ulonglong2*>(mrow + 32);
            ulonglong2 m2 = *reinterpret_cast<const ulonglong2*>(mrow + 64);
            ulonglong2 m3 = *reinterpret_cast<const ulonglong2*>(mrow + 96);
            const float* xrow = &sX[c * 256 + 8 * tg];
            ulonglong2 xa = *reinterpret_cast<const ulonglong2*>(xrow);
            ulonglong2 xc = *reinterpret_cast<const ulonglong2*>(xrow + 4);
            fma2(acc[0][0], m0.x, xa.x); fma2(acc[0][1], m0.x, xa.y);
            fma2(acc[0][2], m0.x, xc.x); fma2(acc[0][3], m0.x, xc.y);
            fma2(acc[1][0], m0.y, xa.x); fma2(acc[1][1], m0.y, xa.y);
            fma2(acc[1][2], m0.y, xc.x); fma2(acc[1][3], m0.y, xc.y);
            fma2(acc[2][0], m1.x, xa.x); fma2(acc[2][1], m1.x, xa.y);
            fma2(acc[2][2], m1.x, xc.x); fma2(acc[2][3], m1.x, xc.y);
            fma2(acc[3][0], m1.y, xa.x); fma2(acc[3][1], m1.y, xa.y);
            fma2(acc[3][2], m1.y, xc.x); fma2(acc[3][3], m1.y, xc.y);
            fma2(acc[4][0], m2.x, xa.x); fma2(acc[4][1], m2.x, xa.y);
            fma2(acc[4][2], m2.x, xc.x); fma2(acc[4][3], m2.x, xc.y);
            fma2(acc[5][0], m2.y, xa.x); fma2(acc[5][1], m2.y, xa.y);
            fma2(acc[5][2], m2.y, xc.x); fma2(acc[5][3], m2.y, xc.y);
            fma2(acc[6][0], m3.x, xa.x); fma2(acc[6][1], m3.x, xa.y);
            fma2(acc[6][2], m3.x, xc.x); fma2(acc[6][3], m3.x, xc.y);
            fma2(acc[7][0], m3.y, xa.x); fma2(acc[7][1], m3.y, xa.y);
            fma2(acc[7][2], m3.y, xc.x); fma2(acc[7][3], m3.y, xc.y);
        }

        // per-token stats (packed over token pairs), butterfly over 8 og-lanes
        unsigned long long ps[4], pq[4];
#pragma unroll
        for (int tp = 0; tp < 4; tp++) {
            ps[tp] = acc[0][tp];
            pq[tp] = mul2(acc[0][tp], acc[0][tp]);
#pragma unroll
            for (int o = 1; o < 8; o++) {
                ps[tp] = add2(ps[tp], acc[o][tp]);
                fma2(pq[tp], acc[o][tp], acc[o][tp]);
            }
        }
#pragma unroll
        for (int m = 1; m < 8; m <<= 1) {
#pragma unroll
            for (int tp = 0; tp < 4; tp++) {
                ps[tp] = add2(ps[tp], __shfl_xor_sync(0xffffffffu, ps[tp], m));
                pq[tp] = add2(pq[tp], __shfl_xor_sync(0xffffffffu, pq[tp], m));
            }
        }

        unsigned long long s2[4], o2[4];
#pragma unroll
        for (int tp = 0; tp < 4; tp++) {
            float slo, shi, qlo, qhi;
            unpk(ps[tp], slo, shi);
            unpk(pq[tp], qlo, qhi);
            float mlo = slo * (1.0f / 64.0f), mhi = shi * (1.0f / 64.0f);
            float ilo = rsqrtf(qlo * (1.0f / 64.0f) - mlo * mlo + 1e-5f);
            float ihi = rsqrtf(qhi * (1.0f / 64.0f) - mhi * mhi + 1e-5f);
            s2[tp] = pk2(ilo, ihi);
            o2[tp] = pk2(-mlo * ilo, -mhi * ihi);
        }

        float4 gv0 = *reinterpret_cast<const float4*>(gain + 8 * og);
        float4 gv1 = *reinterpret_cast<const float4*>(gain + 8 * og + 4);
        float gg[8] = {gv0.x, gv0.y, gv0.z, gv0.w, gv1.x, gv1.y, gv1.z, gv1.w};
#pragma unroll
        for (int o = 0; o < 8; o++) {
            unsigned long long gd = dup2(gg[o]);
            unsigned long long r[4];
#pragma unroll
            for (int tp = 0; tp < 4; tp++) {
                unsigned long long t = o2[tp];
                fma2(t, acc[o][tp], s2[tp]);
                r[tp] = mul2(t, gd);
            }
            float* dst = ob + (size_t)(8 * og + o) * N_TOK + base + 8 * tg;
            ulonglong2 w0; w0.x = r[0]; w0.y = r[1];
            ulonglong2 w1; w1.x = r[2]; w1.y = r[3];
            *reinterpret_cast<ulonglong2*>(dst)     = w0;
            *reinterpret_cast<ulonglong2*>(dst + 4) = w1;
        }
    }
}

// ---------------------------------------------------------------------------
extern "C" void kernel_launch(void* const* d_in, const int* in_sizes, int n_in,
                              void* d_out, int out_size) {
    const float* x     = (const float*)d_in[0];
    const float* w_qkv = (const float*)d_in[1];
    const float* w_out = (const float*)d_in[2];
    const float* b_out = (const float*)d_in[3];
    const float* g     = (const float*)d_in[4];
    float* out = (float*)d_out;

    cudaFuncSetAttribute(gram_kernel,  cudaFuncAttributeMaxDynamicSharedMemorySize, GRAM_SMEM);
    cudaFuncSetAttribute(apply_kernel, cudaFuncAttributeMaxDynamicSharedMemorySize, APPLY_SMEM);

    zero_kernel<<<32, 256>>>();
    gram_kernel<<<dim3(148, 2), 256, GRAM_SMEM>>>(x);
    combine_kernel<<<dim3(4, 2), 256>>>(w_qkv, w_out);
    apply_kernel<<<dim3(148, 2), 256, APPLY_SMEM>>>(x, b_out, g, out);
}

// round 3
// speedup vs baseline: 1.0201x; 1.0005x over previous
#include <cuda_runtime.h>

#define N_TOK 262144            // 64*64*64 tokens per batch
#define NCH   64

__device__ float g_S [2 * 4096];
__device__ float g_Mt[2 * 4096];   // M transposed: [c][o], o contiguous

// ---- f32x2 packed helpers (only reachable via PTX) ------------------------
static __device__ __forceinline__ unsigned long long dup2(float v) {
    unsigned long long r;
    asm("mov.b64 %0,{%1,%1};" : "=l"(r) : "f"(v));
    return r;
}
static __device__ __forceinline__ unsigned long long pk2(float lo, float hi) {
    unsigned long long r;
    asm("mov.b64 %0,{%1,%2};" : "=l"(r) : "f"(lo), "f"(hi));
    return r;
}
static __device__ __forceinline__ void fma2(unsigned long long& d,
                                            unsigned long long a,
                                            unsigned long long b) {
    asm("fma.rn.f32x2 %0, %1, %2, %0;" : "+l"(d) : "l"(a), "l"(b));
}
static __device__ __forceinline__ unsigned long long add2(unsigned long long a,
                                                          unsigned long long b) {
    unsigned long long d;
    asm("add.rn.f32x2 %0,%1,%2;" : "=l"(d) : "l"(a), "l"(b));
    return d;
}
static __device__ __forceinline__ unsigned long long mul2(unsigned long long a,
                                                          unsigned long long b) {
    unsigned long long d;
    asm("mul.rn.f32x2 %0,%1,%2;" : "=l"(d) : "l"(a), "l"(b));
    return d;
}
static __device__ __forceinline__ void unpk(unsigned long long v, float& lo, float& hi) {
    asm("mov.b64 {%0,%1},%2;" : "=f"(lo), "=f"(hi) : "l"(v));
}

// ---------------------------------------------------------------------------
__global__ void zero_kernel() {
    int i = blockIdx.x * 256 + threadIdx.x;
    if (i < 2 * 4096) {
        g_S[i]  = 0.0f;
        g_Mt[i] = 0.0f;
    }
}

// ---------------------------------------------------------------------------
// Pass A: S_b = X_b X_b^T. Persistent blocks (148 per batch).
// 8x8 patch per thread, tokens split 4 ways (s), block-level smem reduction,
// one atomicAdd per element per block.
// smem: sx[64*68] (token-major tile) + sred[4][64*66]
// ---------------------------------------------------------------------------
#define GRAM_SMEM ((4352 + 4 * 4224) * 4)   // 84992 bytes

__global__ void __launch_bounds__(256, 2) gram_kernel(const float* __restrict__ x) {
    extern __shared__ float sm[];
    float* sx   = sm;          // 64 rows * 68 pad
    float* sred = sm + 4352;   // 4 copies * 64 rows * 66 pad

    const int b   = blockIdx.y;
    const float* xb = x + (size_t)b * NCH * N_TOK;
    const int tid = threadIdx.x;
    const int pi  = tid & 7;
    const int pj  = (tid >> 3) & 7;
    const int s   = tid >> 6;

    unsigned long long acc[8][4];
#pragma unroll
    for (int i = 0; i < 8; i++)
#pragma unroll
        for (int jp = 0; jp < 4; jp++) acc[i][jp] = 0ull;

    for (int tile = blockIdx.x; tile < N_TOK / 64; tile += 148) {
        const int base = tile * 64;
        __syncthreads();
        // load 64ch x 64tok, transpose to token-major
#pragma unroll
        for (int k = 0; k < 4; k++) {
            int idx = k * 256 + tid;
            int c   = idx >> 4;
            int t4  = (idx & 15) << 2;
            float4 v = *reinterpret_cast<const float4*>(xb + (size_t)c * N_TOK + base + t4);
            sx[(t4 + 0) * 68 + c] = v.x;
            sx[(t4 + 1) * 68 + c] = v.y;
            sx[(t4 + 2) * 68 + c] = v.z;
            sx[(t4 + 3) * 68 + c] = v.w;
        }
        __syncthreads();
#pragma unroll 4
        for (int tt = 0; tt < 16; tt++) {
            const float* row = &sx[(4 * tt + s) * 68];
            float4 a0     = *reinterpret_cast<const float4*>(row + 8 * pi);
            float4 a1     = *reinterpret_cast<const float4*>(row + 8 * pi + 4);
            ulonglong2 b0 = *reinterpret_cast<const ulonglong2*>(row + 8 * pj);
            ulonglong2 b1 = *reinterpret_cast<const ulonglong2*>(row + 8 * pj + 4);
            unsigned long long d0 = dup2(a0.x), d1 = dup2(a0.y);
            unsigned long long d2 = dup2(a0.z), d3 = dup2(a0.w);
            unsigned long long d4 = dup2(a1.x), d5 = dup2(a1.y);
            unsigned long long d6 = dup2(a1.z), d7 = dup2(a1.w);
            fma2(acc[0][0], d0, b0.x); fma2(acc[0][1], d0, b0.y);
            fma2(acc[0][2], d0, b1.x); fma2(acc[0][3], d0, b1.y);
            fma2(acc[1][0], d1, b0.x); fma2(acc[1][1], d1, b0.y);
            fma2(acc[1][2], d1, b1.x); fma2(acc[1][3], d1, b1.y);
            fma2(acc[2][0], d2, b0.x); fma2(acc[2][1], d2, b0.y);
            fma2(acc[2][2], d2, b1.x); fma2(acc[2][3], d2, b1.y);
            fma2(acc[3][0], d3, b0.x); fma2(acc[3][1], d3, b0.y);
            fma2(acc[3][2], d3, b1.x); fma2(acc[3][3], d3, b1.y);
            fma2(acc[4][0], d4, b0.x); fma2(acc[4][1], d4, b0.y);
            fma2(acc[4][2], d4, b1.x); fma2(acc[4][3], d4, b1.y);
            fma2(acc[5][0], d5, b0.x); fma2(acc[5][1], d5, b0.y);
            fma2(acc[5][2], d5, b1.x); fma2(acc[5][3], d5, b1.y);
            fma2(acc[6][0], d6, b0.x); fma2(acc[6][1], d6, b0.y);
            fma2(acc[6][2], d6, b1.x); fma2(acc[6][3], d6, b1.y);
            fma2(acc[7][0], d7, b0.x); fma2(acc[7][1], d7, b0.y);
            fma2(acc[7][2], d7, b1.x); fma2(acc[7][3], d7, b1.y);
        }
    }

    // stage 1: each s-group writes its private padded copy (no conflicts >2-way)
    __syncthreads();
    float* red = sred + s * 4224;
#pragma unroll
    for (int i = 0; i < 8; i++)
#pragma unroll
        for (int jp = 0; jp < 4; jp++)
            *reinterpret_cast<unsigned long long*>(
                &red[(8 * pi + i) * 66 + 8 * pj + 2 * jp]) = acc[i][jp];
    __syncthreads();

    // stage 2: sum 4 copies, one global atomic per element
    float* Sb = g_S + b * 4096;
#pragma unroll
    for (int k = 0; k < 16; k++) {
        int e = k * 256 + tid;
        int r = e >> 6, c = e & 63;
        float v = sred[r * 66 + c] + sred[4224 + r * 66 + c] +
                  sred[2 * 4224 + r * 66 + c] + sred[3 * 4224 + r * 66 + c];
        atomicAdd(&Sb[e], v);
    }
}

// ---------------------------------------------------------------------------
// Pass B: fold weights into M (transposed). One block per (head, batch).
// ---------------------------------------------------------------------------
__global__ void __launch_bounds__(256) combine_kernel(const float* __restrict__ w_qkv,
                                                      const float* __restrict__ w_out) {
    __shared__ float sS[4096];
    __shared__ float sA[2048];
    __shared__ float sC[1024];
    __shared__ float sP[2048];
    const int b = blockIdx.y, h = blockIdx.x;
    const int tid = threadIdx.x;

    const float* Sb = g_S + b * 4096;
    for (int k = tid; k < 4096; k += 256) sS[k] = Sb[k];
    __syncthreads();

    const float* Wq = w_qkv + (h * 32) * 64;
    const float* Wk = w_qkv + (128 + h * 32) * 64;
    const float* Wv = w_qkv + (256 + h * 32) * 64;

    for (int e = tid; e < 2048; e += 256) {
        int ii = e >> 6, c = e & 63;
        float s = 0.0f;
        for (int c2 = 0; c2 < 64; c2++) s += Wk[ii * 64 + c2] * sS[c2 * 64 + c];
        sA[e] = s;
    }
    __syncthreads();

    const float coef = 0.17677669529663688f / 4096.0f;  // 32^-0.5 / (H*W)
    for (int e = tid; e < 1024; e += 256) {
        int ii = e >> 5, jj = e & 31;
        float s = 0.0f;
        for (int c = 0; c < 64; c++) s += sA[ii * 64 + c] * Wv[jj * 64 + c];
        sC[e] = s * coef;
    }
    __syncthreads();

    for (int e = tid; e < 2048; e += 256) {
        int jj = e >> 6, c = e & 63;
        float s = 0.0f;
        for (int ii = 0; ii < 32; ii++) s += sC[ii * 32 + jj] * Wq[ii * 64 + c];
        sP[e] = s;
    }
    __syncthreads();

    float* Mtb = g_Mt + b * 4096;
    for (int e = tid; e < 4096; e += 256) {
        int o = e >> 6, c = e & 63;
        float s = 0.0f;
        for (int jj = 0; jj < 32; jj++) s += w_out[o * 128 + h * 32 + jj] * sP[jj * 64 + c];
        atomicAdd(&Mtb[c * 64 + o], s);
    }
}

// ---------------------------------------------------------------------------
// Pass C: y = M x + b_out, channel LayerNorm * gain.
// Persistent blocks. f32x2 packs TOKEN pairs (x loads pre-packed, zero MOVs);
// M pre-duplicated in smem, chunk-interleaved [c][j][og] for conflict-free LDS.
// Thread (og,tg) owns channels 8og..8og+7 x tokens 8tg..8tg+7.
// smem: sMd[64*128] + sX[64*256]
// ---------------------------------------------------------------------------
#define APPLY_SMEM ((8192 + 16384) * 4)   // 98304 bytes

__global__ void __launch_bounds__(256, 2) apply_kernel(const float* __restrict__ x,
                                                       const float* __restrict__ b_out,
                                                       const float* __restrict__ gain,
                                                       float* __restrict__ out) {
    extern __shared__ float sm[];
    float* sMd = sm;          // [c][j][og][dup-pair]  (64 * 128 floats)
    float* sX  = sm + 8192;   // [c][t]  (64 * 256 floats)

    const int b   = blockIdx.y;
    const int tid = threadIdx.x;
    const float* xb = x + (size_t)b * NCH * N_TOK;
    float*       ob = out + (size_t)b * NCH * N_TOK;
    const float* Mtb = g_Mt + b * 4096;

    // build duplicated, chunk-interleaved M
#pragma unroll
    for (int k = 0; k < 4; k++) {
        int idx = k * 256 + tid;          // float4 index into Mt
        int c   = idx >> 4;
        int a   = idx & 15;               // channels 4a..4a+3
        float4 v = reinterpret_cast<const float4*>(Mtb)[idx];
        int ogw = a >> 1;
        int j0  = (a & 1) * 2;
        float4 w0 = {v.x, v.x, v.y, v.y};
        float4 w1 = {v.z, v.z, v.w, v.w};
        *reinterpret_cast<float4*>(&sMd[c * 128 + j0 * 32 + ogw * 4])       = w0;
        *reinterpret_cast<float4*>(&sMd[c * 128 + (j0 + 1) * 32 + ogw * 4]) = w1;
    }

    const int og = tid & 7;    // channels 8*og..8*og+7
    const int tg = tid >> 3;   // tokens  8*tg..8*tg+7 within tile

    for (int tile = blockIdx.x; tile < N_TOK / 256; tile += 148) {
        const int base = tile * 256;
        __syncthreads();   // sMd ready (1st iter) / sX readers done (later)
#pragma unroll
        for (int k = 0; k < 16; k++) {
            int idx = k * 256 + tid;       // float4 index into tile
            int c   = idx >> 6;
            int t4  = (idx & 63) << 2;
            *reinterpret_cast<float4*>(&sX[c * 256 + t4]) =
                *reinterpret_cast<const float4*>(xb + (size_t)c * N_TOK + base + t4);
        }
        __syncthreads();

        // acc[o][tp] : channel 8og+o, token pair 2tp within this thread's 8 tokens
        unsigned long long acc[8][4];
        {
            float4 bv0 = *reinterpret_cast<const float4*>(b_out + 8 * og);
            float4 bv1 = *reinterpret_cast<const float4*>(b_out + 8 * og + 4);
            float bb[8] = {bv0.x, bv0.y, bv0.z, bv0.w, bv1.x, bv1.y, bv1.z, bv1.w};
#pragma unroll
            for (int o = 0; o < 8; o++) {
                unsigned long long d = dup2(bb[o]);
#pragma unroll
                for (int tp = 0; tp < 4; tp++) acc[o][tp] = d;
            }
        }

#pragma unroll 4
        for (int c = 0; c < 64; c++) {
            const float* mrow = &sMd[c * 128 + og * 4];
            ulonglong2 m0 = *reinterpret_cast<const ulonglong2*>(mrow);
            ulonglong2 m1 = *reinterpret_cast<const ulonglong2*>(mrow + 32);
            ulonglong2 m2 = *reinterpret_cast<const ulonglong2*>(mrow + 64);
            ulonglong2 m3 = *reinterpret_cast<const ulonglong2*>(mrow + 96);
            const float* xrow = &sX[c * 256 + 8 * tg];
            ulonglong2 xa = *reinterpret_cast<const ulonglong2*>(xrow);
            ulonglong2 xc = *reinterpret_cast<const ulonglong2*>(xrow + 4);
            fma2(acc[0][0], m0.x, xa.x); fma2(acc[0][1], m0.x, xa.y);
            fma2(acc[0][2], m0.x, xc.x); fma2(acc[0][3], m0.x, xc.y);
            fma2(acc[1][0], m0.y, xa.x); fma2(acc[1][1], m0.y, xa.y);
            fma2(acc[1][2], m0.y, xc.x); fma2(acc[1][3], m0.y, xc.y);
            fma2(acc[2][0], m1.x, xa.x); fma2(acc[2][1], m1.x, xa.y);
            fma2(acc[2][2], m1.x, xc.x); fma2(acc[2][3], m1.x, xc.y);
            fma2(acc[3][0], m1.y, xa.x); fma2(acc[3][1], m1.y, xa.y);
            fma2(acc[3][2], m1.y, xc.x); fma2(acc[3][3], m1.y, xc.y);
            fma2(acc[4][0], m2.x, xa.x); fma2(acc[4][1], m2.x, xa.y);
            fma2(acc[4][2], m2.x, xc.x); fma2(acc[4][3], m2.x, xc.y);
            fma2(acc[5][0], m2.y, xa.x); fma2(acc[5][1], m2.y, xa.y);
            fma2(acc[5][2], m2.y, xc.x); fma2(acc[5][3], m2.y, xc.y);
            fma2(acc[6][0], m3.x, xa.x); fma2(acc[6][1], m3.x, xa.y);
            fma2(acc[6][2], m3.x, xc.x); fma2(acc[6][3], m3.x, xc.y);
            fma2(acc[7][0], m3.y, xa.x); fma2(acc[7][1], m3.y, xa.y);
            fma2(acc[7][2], m3.y, xc.x); fma2(acc[7][3], m3.y, xc.y);
        }

        // per-token stats (packed over token pairs), butterfly over 8 og-lanes
        unsigned long long ps[4], pq[4];
#pragma unroll
        for (int tp = 0; tp < 4; tp++) {
            ps[tp] = acc[0][tp];
            pq[tp] = mul2(acc[0][tp], acc[0][tp]);
#pragma unroll
            for (int o = 1; o < 8; o++) {
                ps[tp] = add2(ps[tp], acc[o][tp]);
                fma2(pq[tp], acc[o][tp], acc[o][tp]);
            }
        }
#pragma unroll
        for (int m = 1; m < 8; m <<= 1) {
#pragma unroll
            for (int tp = 0; tp < 4; tp++) {
                ps[tp] = add2(ps[tp], __shfl_xor_sync(0xffffffffu, ps[tp], m));
                pq[tp] = add2(pq[tp], __shfl_xor_sync(0xffffffffu, pq[tp], m));
            }
        }

        unsigned long long s2[4], o2[4];
#pragma unroll
        for (int tp = 0; tp < 4; tp++) {
            float slo, shi, qlo, qhi;
            unpk(ps[tp], slo, shi);
            unpk(pq[tp], qlo, qhi);
            float mlo = slo * (1.0f / 64.0f), mhi = shi * (1.0f / 64.0f);
            float ilo = rsqrtf(qlo * (1.0f / 64.0f) - mlo * mlo + 1e-5f);
            float ihi = rsqrtf(qhi * (1.0f / 64.0f) - mhi * mhi + 1e-5f);
            s2[tp] = pk2(ilo, ihi);
            o2[tp] = pk2(-mlo * ilo, -mhi * ihi);
        }

        float4 gv0 = *reinterpret_cast<const float4*>(gain + 8 * og);
        float4 gv1 = *reinterpret_cast<const float4*>(gain + 8 * og + 4);
        float gg[8] = {gv0.x, gv0.y, gv0.z, gv0.w, gv1.x, gv1.y, gv1.z, gv1.w};
#pragma unroll
        for (int o = 0; o < 8; o++) {
            unsigned long long gd = dup2(gg[o]);
            unsigned long long r[4];
#pragma unroll
            for (int tp = 0; tp < 4; tp++) {
                unsigned long long t = o2[tp];
                fma2(t, acc[o][tp], s2[tp]);
                r[tp] = mul2(t, gd);
            }
            float* dst = ob + (size_t)(8 * og + o) * N_TOK + base + 8 * tg;
            ulonglong2 w0; w0.x = r[0]; w0.y = r[1];
            ulonglong2 w1; w1.x = r[2]; w1.y = r[3];
            *reinterpret_cast<ulonglong2*>(dst)     = w0;
            *reinterpret_cast<ulonglong2*>(dst + 4) = w1;
        }
    }
}

// ---------------------------------------------------------------------------
extern "C" void kernel_launch(void* const* d_in, const int* in_sizes, int n_in,
                              void* d_out, int out_size) {
    const float* x     = (const float*)d_in[0];
    const float* w_qkv = (const float*)d_in[1];
    const float* w_out = (const float*)d_in[2];
    const float* b_out = (const float*)d_in[3];
    const float* g     = (const float*)d_in[4];
    float* out = (float*)d_out;

    cudaFuncSetAttribute(gram_kernel,  cudaFuncAttributeMaxDynamicSharedMemorySize, GRAM_SMEM);
    cudaFuncSetAttribute(apply_kernel, cudaFuncAttributeMaxDynamicSharedMemorySize, APPLY_SMEM);

    zero_kernel<<<32, 256>>>();
    gram_kernel<<<dim3(148, 2), 256, GRAM_SMEM>>>(x);
    combine_kernel<<<dim3(4, 2), 256>>>(w_qkv, w_out);
    apply_kernel<<<dim3(148, 2), 256, APPLY_SMEM>>>(x, b_out, g, out);
}

// round 5
// speedup vs baseline: 1.7903x; 1.7549x over previous
#include <cuda_runtime.h>
#include <cuda_bf16.h>
#include <cstdint>

#define N_TOK 262144
#define NCH   64

__device__ float g_S[2 * 4096];
__device__ float g_M[2 * 4096];   // M: [o][c], c contiguous

// ---------------------------------------------------------------------------
static __device__ __forceinline__ uint32_t smem_u32(const void* p) {
    uint32_t a;
    asm("{ .reg .u64 t; cvta.to.shared.u64 t, %1; cvt.u32.u64 %0, t; }" : "=r"(a) : "l"(p));
    return a;
}
static __device__ __forceinline__ void ldsm4(uint32_t (&r)[4], uint32_t a) {
    asm volatile("ldmatrix.sync.aligned.m8n8.x4.shared.b16 {%0,%1,%2,%3}, [%4];"
                 : "=r"(r[0]), "=r"(r[1]), "=r"(r[2]), "=r"(r[3]) : "r"(a));
}
static __device__ __forceinline__ void mma16816(float (&d)[4], const uint32_t (&a)[4],
                                                uint32_t b0, uint32_t b1) {
    asm volatile("mma.sync.aligned.m16n8k16.row.col.f32.bf16.bf16.f32 "
                 "{%0,%1,%2,%3},{%4,%5,%6,%7},{%8,%9},{%0,%1,%2,%3};"
                 : "+f"(d[0]), "+f"(d[1]), "+f"(d[2]), "+f"(d[3])
                 : "r"(a[0]), "r"(a[1]), "r"(a[2]), "r"(a[3]), "r"(b0), "r"(b1));
}
static __device__ __forceinline__ uint32_t pkbf(float a, float b) {
    __nv_bfloat162 t;
    t.x = __float2bfloat16(a);
    t.y = __float2bfloat16(b);
    return *reinterpret_cast<uint32_t*>(&t);
}
static __device__ __forceinline__ void split2(float a, float b, uint32_t& hi, uint32_t& lo) {
    __nv_bfloat16 ha = __float2bfloat16(a), hb = __float2bfloat16(b);
    float ra = a - __bfloat162float(ha), rb = b - __bfloat162float(hb);
    __nv_bfloat162 h; h.x = ha; h.y = hb;
    hi = *reinterpret_cast<uint32_t*>(&h);
    lo = pkbf(ra, rb);
}

// ---------------------------------------------------------------------------
__global__ void zero_kernel() {
    int i = blockIdx.x * 256 + threadIdx.x;
    if (i < 2 * 4096) { g_S[i] = 0.0f; g_M[i] = 0.0f; }
}

// ---------------------------------------------------------------------------
// Pass A: per 128-token tile, smem = [128 rows: ch-hi 0-63, ch-lo 64-127][128 tok]
// bf16, row stride 272B. Warp w owns m-stripe rows 16w..16w+15, accumulates
// D[stripe][64] in registers across ALL its tiles (k = tokens, B = Xh rows).
// S[i][j] = Dt[i][j] + Db[i][j] + Db[j][i]   (drops Xl·Xl^T ~4e-6 rel)
// Epilogue: stage D to smem (reused as float[128][68]), combine, one atomic.
// ---------------------------------------------------------------------------
#define GRAM_SMEM 34816

__global__ void __launch_bounds__(256, 2) gram_kernel(const float* __restrict__ x) {
    extern __shared__ char smem[];
    const uint32_t sb = smem_u32(smem);
    const int tid = threadIdx.x, wid = tid >> 5, lane = tid & 31;
    const int b = blockIdx.y;
    const float* xb = x + (size_t)b * NCH * N_TOK;

    float d[8][4];
#pragma unroll
    for (int nn = 0; nn < 8; nn++)
#pragma unroll
        for (int r = 0; r < 4; r++) d[nn][r] = 0.0f;

    const uint32_t aAddr = sb + (16 * wid + (lane & 15)) * 272 + ((lane >> 4) & 1) * 16;

    for (int tile = blockIdx.x; tile < N_TOK / 128; tile += gridDim.x) {
        const int base = tile * 128;
        __syncthreads();
#pragma unroll
        for (int k = 0; k < 8; k++) {
            int idx = k * 256 + tid;
            int c = idx >> 5, t4 = (idx & 31) << 2;
            float4 v = *reinterpret_cast<const float4*>(xb + (size_t)c * N_TOK + base + t4);
            uint32_t h0, l0, h1, l1;
            split2(v.x, v.y, h0, l0);
            split2(v.z, v.w, h1, l1);
            uint2 hw; hw.x = h0; hw.y = h1;
            uint2 lw; lw.x = l0; lw.y = l1;
            *reinterpret_cast<uint2*>(smem + c * 272 + t4 * 2) = hw;
            *reinterpret_cast<uint2*>(smem + (64 + c) * 272 + t4 * 2) = lw;
        }
        __syncthreads();
#pragma unroll
        for (int k = 0; k < 8; k++) {
            uint32_t af[4];
            ldsm4(af, aAddr + k * 32);
#pragma unroll
            for (int nn2 = 0; nn2 < 4; nn2++) {
                uint32_t bf[4];
                ldsm4(bf, sb + (16 * nn2 + (lane & 15)) * 272 + ((lane >> 4) & 1) * 16 + k * 32);
                mma16816(d[2 * nn2],     af, bf[0], bf[2]);
                mma16816(d[2 * nn2 + 1], af, bf[1], bf[3]);
            }
        }
    }

    // stage D to smem (reuse tile buffer as float[128][68])
    __syncthreads();
    float* sf = reinterpret_cast<float*>(smem);
    const int row0 = 16 * wid + (lane >> 2);
    const int col0 = 2 * (lane & 3);
#pragma unroll
    for (int nn = 0; nn < 8; nn++) {
        sf[row0 * 68 + 8 * nn + col0]           = d[nn][0];
        sf[row0 * 68 + 8 * nn + col0 + 1]       = d[nn][1];
        sf[(row0 + 8) * 68 + 8 * nn + col0]     = d[nn][2];
        sf[(row0 + 8) * 68 + 8 * nn + col0 + 1] = d[nn][3];
    }
    __syncthreads();

    float* Sb = g_S + b * 4096;
#pragma unroll
    for (int kk = 0; kk < 16; kk++) {
        int e = kk * 256 + tid;
        int i = e >> 6, j = e & 63;
        float v = sf[i * 68 + j] + sf[(64 + i) * 68 + j] + sf[(64 + j) * 68 + i];
        atomicAdd(&Sb[e], v);
    }
}

// ---------------------------------------------------------------------------
// Pass B: fold weights into M[o][c]. One block per (head, batch).
// ---------------------------------------------------------------------------
__global__ void __launch_bounds__(256) combine_kernel(const float* __restrict__ w_qkv,
                                                      const float* __restrict__ w_out) {
    __shared__ float sS[4096];
    __shared__ float sA[2048];
    __shared__ float sC[1024];
    __shared__ float sP[2048];
    const int b = blockIdx.y, h = blockIdx.x;
    const int tid = threadIdx.x;

    const float* Sb = g_S + b * 4096;
    for (int k = tid; k < 4096; k += 256) sS[k] = Sb[k];
    __syncthreads();

    const float* Wq = w_qkv + (h * 32) * 64;
    const float* Wk = w_qkv + (128 + h * 32) * 64;
    const float* Wv = w_qkv + (256 + h * 32) * 64;

    for (int e = tid; e < 2048; e += 256) {
        int ii = e >> 6, c = e & 63;
        float s = 0.0f;
        for (int c2 = 0; c2 < 64; c2++) s += Wk[ii * 64 + c2] * sS[c2 * 64 + c];
        sA[e] = s;
    }
    __syncthreads();

    const float coef = 0.17677669529663688f / 4096.0f;
    for (int e = tid; e < 1024; e += 256) {
        int ii = e >> 5, jj = e & 31;
        float s = 0.0f;
        for (int c = 0; c < 64; c++) s += sA[ii * 64 + c] * Wv[jj * 64 + c];
        sC[e] = s * coef;
    }
    __syncthreads();

    for (int e = tid; e < 2048; e += 256) {
        int jj = e >> 6, c = e & 63;
        float s = 0.0f;
        for (int ii = 0; ii < 32; ii++) s += sC[ii * 32 + jj] * Wq[ii * 64 + c];
        sP[e] = s;
    }
    __syncthreads();

    float* Mb = g_M + b * 4096;
    for (int e = tid; e < 4096; e += 256) {
        int o = e >> 6, c = e & 63;
        float s = 0.0f;
        for (int jj = 0; jj < 32; jj++) s += w_out[o * 128 + h * 32 + jj] * sP[jj * 64 + c];
        atomicAdd(&Mb[e], s);
    }
}

// ---------------------------------------------------------------------------
// Pass C: stationary A = [[Mh, Mh],[Ml, 0]] (128x128 bf16, rows o', k=ch hi|lo)
// per tile B = x^T rows [t][k=128] (hi 0-63, lo 64-127). D = A·B^T:
//   y[o][t] = D[o][t] + D[o+64][t] = Mh·x + Ml·xh  (error ~ Ml·xl ~4e-6)
// Warp owns 16 tokens; mma skips the zero block (m>=4 & k>=4).
// LayerNorm: 3-shfl butterfly over lane>>2 groups; direct STG per element.
// smem: A at 0 (34816B), X at 34816 (34816B); both row stride 272B.
// ---------------------------------------------------------------------------
#define APPLY_SMEM (34816 * 2)

__global__ void __launch_bounds__(256, 2) apply_kernel(const float* __restrict__ x,
                                                       const float* __restrict__ b_out,
                                                       const float* __restrict__ gain,
                                                       float* __restrict__ out) {
    extern __shared__ char smem[];
    const uint32_t sb = smem_u32(smem);
    const int tid = threadIdx.x, wid = tid >> 5, lane = tid & 31;
    const int b = blockIdx.y;
    const float* xb = x + (size_t)b * NCH * N_TOK;
    float* ob = out + (size_t)b * NCH * N_TOK;

    // build stationary A from g_M
    {
        const float* Mb = g_M + b * 4096;
        __nv_bfloat16* pa = reinterpret_cast<__nv_bfloat16*>(smem);
        for (int e = tid; e < 4096; e += 256) {
            int o = e >> 6, c = e & 63;
            float m = Mb[e];
            __nv_bfloat16 h = __float2bfloat16(m);
            __nv_bfloat16 l = __float2bfloat16(m - __bfloat162float(h));
            pa[o * 136 + c]        = h;
            pa[o * 136 + 64 + c]   = h;
            pa[(64 + o) * 136 + c] = l;   // cols 64-127 of bottom never read
        }
    }

    const int row = lane >> 2;
    float bb[4][2], gg[4][2];
#pragma unroll
    for (int m = 0; m < 4; m++)
#pragma unroll
        for (int rh = 0; rh < 2; rh++) {
            int o = 16 * m + row + 8 * rh;
            bb[m][rh] = b_out[o];
            gg[m][rh] = gain[o];
        }

    const int t  = tid & 127;
    const int c0 = (tid >> 7) * 32;
    const int tw = 16 * wid;
    const uint32_t xBa = sb + 34816 + (tw + (lane & 15)) * 272 + ((lane >> 4) & 1) * 16;
    const uint32_t aBa = sb + (lane & 15) * 272 + ((lane >> 4) & 1) * 16;

    for (int tile = blockIdx.x; tile < N_TOK / 128; tile += gridDim.x) {
        const int base = tile * 128;
        __syncthreads();

        // load 32 channels of one token, split hi/lo, store token-row
        {
            float v[32];
#pragma unroll
            for (int q = 0; q < 32; q++)
                v[q] = xb[(size_t)(c0 + q) * N_TOK + base + t];
            uint32_t hw[16], lw[16];
#pragma unroll
            for (int q = 0; q < 16; q++) split2(v[2 * q], v[2 * q + 1], hw[q], lw[q]);
            char* xr = smem + 34816 + t * 272 + c0 * 2;
#pragma unroll
            for (int j = 0; j < 4; j++) {
                uint4 w; w.x = hw[4 * j]; w.y = hw[4 * j + 1]; w.z = hw[4 * j + 2]; w.w = hw[4 * j + 3];
                *reinterpret_cast<uint4*>(xr + 16 * j) = w;
            }
#pragma unroll
            for (int j = 0; j < 4; j++) {
                uint4 w; w.x = lw[4 * j]; w.y = lw[4 * j + 1]; w.z = lw[4 * j + 2]; w.w = lw[4 * j + 3];
                *reinterpret_cast<uint4*>(xr + 128 + 16 * j) = w;
            }
        }
        __syncthreads();

        float d[8][2][4];
#pragma unroll
        for (int m = 0; m < 8; m++)
#pragma unroll
            for (int nn = 0; nn < 2; nn++)
#pragma unroll
                for (int r = 0; r < 4; r++) d[m][nn][r] = 0.0f;

#pragma unroll
        for (int k = 0; k < 8; k++) {
            uint32_t bf[4];
            ldsm4(bf, xBa + k * 32);
            const int mm = (k < 4) ? 8 : 4;
#pragma unroll
            for (int m = 0; m < 8; m++) {
                if (m >= mm) break;
                uint32_t af[4];
                ldsm4(af, aBa + m * (16 * 272) + k * 32);
                mma16816(d[m][0], af, bf[0], bf[2]);
                mma16816(d[m][1], af, bf[1], bf[3]);
            }
        }

        // epilogue: fold halves + bias, per-token stats, normalize, store
        float yy[4][2][4];
        float s[2][2] = {{0.f, 0.f}, {0.f, 0.f}};
        float qq[2][2] = {{0.f, 0.f}, {0.f, 0.f}};
#pragma unroll
        for (int m = 0; m < 4; m++)
#pragma unroll
            for (int nn = 0; nn < 2; nn++)
#pragma unroll
                for (int r = 0; r < 4; r++) {
                    float v = d[m][nn][r] + d[m + 4][nn][r] + bb[m][r >> 1];
                    yy[m][nn][r] = v;
                    s[nn][r & 1] += v;
                    qq[nn][r & 1] += v * v;
                }
#pragma unroll
        for (int mask = 4; mask < 32; mask <<= 1)
#pragma unroll
            for (int nn = 0; nn < 2; nn++)
#pragma unroll
                for (int p = 0; p < 2; p++) {
                    s[nn][p]  += __shfl_xor_sync(0xffffffffu, s[nn][p], mask);
                    qq[nn][p] += __shfl_xor_sync(0xffffffffu, qq[nn][p], mask);
                }
        float mean[2][2], istd[2][2];
#pragma unroll
        for (int nn = 0; nn < 2; nn++)
#pragma unroll
            for (int p = 0; p < 2; p++) {
                float mu = s[nn][p] * (1.0f / 64.0f);
                mean[nn][p] = mu;
                istd[nn][p] = rsqrtf(qq[nn][p] * (1.0f / 64.0f) - mu * mu + 1e-5f);
            }

        float* obp = ob + base;
#pragma unroll
        for (int m = 0; m < 4; m++)
#pragma unroll
            for (int nn = 0; nn < 2; nn++)
#pragma unroll
                for (int r = 0; r < 4; r++) {
                    int o  = 16 * m + row + 8 * (r >> 1);
                    int tt = tw + 8 * nn + 2 * (lane & 3) + (r & 1);
                    obp[(size_t)o * N_TOK + tt] =
                        (yy[m][nn][r] - mean[nn][r & 1]) * istd[nn][r & 1] * gg[m][r >> 1];
                }
    }
}

// ---------------------------------------------------------------------------
extern "C" void kernel_launch(void* const* d_in, const int* in_sizes, int n_in,
                              void* d_out, int out_size) {
    const float* x     = (const float*)d_in[0];
    const float* w_qkv = (const float*)d_in[1];
    const float* w_out = (const float*)d_in[2];
    const float* b_out = (const float*)d_in[3];
    const float* g     = (const float*)d_in[4];
    float* out = (float*)d_out;

    cudaFuncSetAttribute(apply_kernel, cudaFuncAttributeMaxDynamicSharedMemorySize, APPLY_SMEM);

    zero_kernel<<<32, 256>>>();
    gram_kernel<<<dim3(296, 2), 256, GRAM_SMEM>>>(x);
    combine_kernel<<<dim3(4, 2), 256>>>(w_qkv, w_out);
    apply_kernel<<<dim3(296, 2), 256, APPLY_SMEM>>>(x, b_out, g, out);
}

// round 6
// speedup vs baseline: 2.0905x; 1.1677x over previous
#include <cuda_runtime.h>
#include <cuda_bf16.h>
#include <cstdint>

#define N_TOK 262144
#define NCH   64

__device__ float g_S[2 * 4096];
__device__ float g_M[2 * 4096];   // M: [o][c], c contiguous

// ---------------------------------------------------------------------------
static __device__ __forceinline__ uint32_t smem_u32(const void* p) {
    uint32_t a;
    asm("{ .reg .u64 t; cvta.to.shared.u64 t, %1; cvt.u32.u64 %0, t; }" : "=r"(a) : "l"(p));
    return a;
}
static __device__ __forceinline__ void ldsm4(uint32_t (&r)[4], uint32_t a) {
    asm volatile("ldmatrix.sync.aligned.m8n8.x4.shared.b16 {%0,%1,%2,%3}, [%4];"
                 : "=r"(r[0]), "=r"(r[1]), "=r"(r[2]), "=r"(r[3]) : "r"(a));
}
static __device__ __forceinline__ void ldsm4t(uint32_t (&r)[4], uint32_t a) {
    asm volatile("ldmatrix.sync.aligned.m8n8.x4.trans.shared.b16 {%0,%1,%2,%3}, [%4];"
                 : "=r"(r[0]), "=r"(r[1]), "=r"(r[2]), "=r"(r[3]) : "r"(a));
}
static __device__ __forceinline__ void mma16816(float (&d)[4], const uint32_t (&a)[4],
                                                uint32_t b0, uint32_t b1) {
    asm volatile("mma.sync.aligned.m16n8k16.row.col.f32.bf16.bf16.f32 "
                 "{%0,%1,%2,%3},{%4,%5,%6,%7},{%8,%9},{%0,%1,%2,%3};"
                 : "+f"(d[0]), "+f"(d[1]), "+f"(d[2]), "+f"(d[3])
                 : "r"(a[0]), "r"(a[1]), "r"(a[2]), "r"(a[3]), "r"(b0), "r"(b1));
}
static __device__ __forceinline__ uint32_t pkbf(float a, float b) {
    __nv_bfloat162 t;
    t.x = __float2bfloat16(a);
    t.y = __float2bfloat16(b);
    return *reinterpret_cast<uint32_t*>(&t);
}
static __device__ __forceinline__ void split2(float a, float b, uint32_t& hi, uint32_t& lo) {
    __nv_bfloat16 ha = __float2bfloat16(a), hb = __float2bfloat16(b);
    float ra = a - __bfloat162float(ha), rb = b - __bfloat162float(hb);
    __nv_bfloat162 h; h.x = ha; h.y = hb;
    hi = *reinterpret_cast<uint32_t*>(&h);
    lo = pkbf(ra, rb);
}
static __device__ __forceinline__ void stcs2(float* p, float a, float b) {
    asm volatile("st.global.cs.v2.f32 [%0], {%1,%2};" :: "l"(p), "f"(a), "f"(b) : "memory");
}

// ---------------------------------------------------------------------------
__global__ void zero_kernel() {
    int i = blockIdx.x * 256 + threadIdx.x;
    if (i < 2 * 4096) { g_S[i] = 0.0f; g_M[i] = 0.0f; }
}

// ---------------------------------------------------------------------------
// Pass A: tile smem = [128 rows: ch-hi 0-63, ch-lo 64-127][128 tok] bf16,
// row stride 272B. Warp w: m-stripe rows 16w..16w+15, D[stripe][64] in regs
// across all tiles (B = Xh rows). S = Dt + Db + Db^T (drops Xl·Xl^T ~4e-6).
// Software-pipelined: next tile's LDGs issued before the mma phase.
// ---------------------------------------------------------------------------
#define GRAM_SMEM 34816

__global__ void __launch_bounds__(256, 2) gram_kernel(const float* __restrict__ x) {
    extern __shared__ char smem[];
    const uint32_t sb = smem_u32(smem);
    const int tid = threadIdx.x, wid = tid >> 5, lane = tid & 31;
    const int b = blockIdx.y;
    const float* xb = x + (size_t)b * NCH * N_TOK;

    float d[8][4];
#pragma unroll
    for (int nn = 0; nn < 8; nn++)
#pragma unroll
        for (int r = 0; r < 4; r++) d[nn][r] = 0.0f;

    const uint32_t aAddr = sb + (16 * wid + (lane & 15)) * 272 + ((lane >> 4) & 1) * 16;
    const int c_ld  = tid >> 3;            // channel this thread loads (float4 id)
    const int t4_ld = (tid & 7) << 4;      // token*... (tid&7)*4 tokens? see below

    // each thread: 8 float4 loads covering (c = tid>>5 + 8k rows? ) -- use k-loop
    float4 v[8];
    int tile = blockIdx.x;
#pragma unroll
    for (int k = 0; k < 8; k++) {
        int idx = k * 256 + tid;
        int c = idx >> 5, t4 = (idx & 31) << 2;
        v[k] = *reinterpret_cast<const float4*>(xb + (size_t)c * N_TOK + tile * 128 + t4);
    }

    for (; tile < N_TOK / 128; tile += gridDim.x) {
        __syncthreads();
#pragma unroll
        for (int k = 0; k < 8; k++) {
            int idx = k * 256 + tid;
            int c = idx >> 5, t4 = (idx & 31) << 2;
            uint32_t h0, l0, h1, l1;
            split2(v[k].x, v[k].y, h0, l0);
            split2(v[k].z, v[k].w, h1, l1);
            uint2 hw; hw.x = h0; hw.y = h1;
            uint2 lw; lw.x = l0; lw.y = l1;
            *reinterpret_cast<uint2*>(smem + c * 272 + t4 * 2) = hw;
            *reinterpret_cast<uint2*>(smem + (64 + c) * 272 + t4 * 2) = lw;
        }
        __syncthreads();

        // prefetch next tile while mma runs
        const int ntile = tile + gridDim.x;
        if (ntile < N_TOK / 128) {
#pragma unroll
            for (int k = 0; k < 8; k++) {
                int idx = k * 256 + tid;
                int c = idx >> 5, t4 = (idx & 31) << 2;
                v[k] = *reinterpret_cast<const float4*>(xb + (size_t)c * N_TOK + ntile * 128 + t4);
            }
        }

#pragma unroll
        for (int k = 0; k < 8; k++) {
            uint32_t af[4];
            ldsm4(af, aAddr + k * 32);
#pragma unroll
            for (int nn2 = 0; nn2 < 4; nn2++) {
                uint32_t bf[4];
                ldsm4(bf, sb + (16 * nn2 + (lane & 15)) * 272 + ((lane >> 4) & 1) * 16 + k * 32);
                mma16816(d[2 * nn2],     af, bf[0], bf[2]);
                mma16816(d[2 * nn2 + 1], af, bf[1], bf[3]);
            }
        }
    }

    // stage D to smem (reuse tile buffer as float[128][68])
    __syncthreads();
    float* sf = reinterpret_cast<float*>(smem);
    const int row0 = 16 * wid + (lane >> 2);
    const int col0 = 2 * (lane & 3);
#pragma unroll
    for (int nn = 0; nn < 8; nn++) {
        sf[row0 * 68 + 8 * nn + col0]           = d[nn][0];
        sf[row0 * 68 + 8 * nn + col0 + 1]       = d[nn][1];
        sf[(row0 + 8) * 68 + 8 * nn + col0]     = d[nn][2];
        sf[(row0 + 8) * 68 + 8 * nn + col0 + 1] = d[nn][3];
    }
    __syncthreads();

    float* Sb = g_S + b * 4096;
#pragma unroll
    for (int kk = 0; kk < 16; kk++) {
        int e = kk * 256 + tid;
        int i = e >> 6, j = e & 63;
        float vv = sf[i * 68 + j] + sf[(64 + i) * 68 + j] + sf[(64 + j) * 68 + i];
        atomicAdd(&Sb[e], vv);
    }
}

// ---------------------------------------------------------------------------
// Pass B: fold weights into M[o][c]. One block per (head, batch).
// ---------------------------------------------------------------------------
__global__ void __launch_bounds__(256) combine_kernel(const float* __restrict__ w_qkv,
                                                      const float* __restrict__ w_out) {
    __shared__ float sS[4096];
    __shared__ float sA[2048];
    __shared__ float sC[1024];
    __shared__ float sP[2048];
    const int b = blockIdx.y, h = blockIdx.x;
    const int tid = threadIdx.x;

    const float* Sb = g_S + b * 4096;
    for (int k = tid; k < 4096; k += 256) sS[k] = Sb[k];
    __syncthreads();

    const float* Wq = w_qkv + (h * 32) * 64;
    const float* Wk = w_qkv + (128 + h * 32) * 64;
    const float* Wv = w_qkv + (256 + h * 32) * 64;

    for (int e = tid; e < 2048; e += 256) {
        int ii = e >> 6, c = e & 63;
        float s = 0.0f;
        for (int c2 = 0; c2 < 64; c2++) s += Wk[ii * 64 + c2] * sS[c2 * 64 + c];
        sA[e] = s;
    }
    __syncthreads();

    const float coef = 0.17677669529663688f / 4096.0f;
    for (int e = tid; e < 1024; e += 256) {
        int ii = e >> 5, jj = e & 31;
        float s = 0.0f;
        for (int c = 0; c < 64; c++) s += sA[ii * 64 + c] * Wv[jj * 64 + c];
        sC[e] = s * coef;
    }
    __syncthreads();

    for (int e = tid; e < 2048; e += 256) {
        int jj = e >> 6, c = e & 63;
        float s = 0.0f;
        for (int ii = 0; ii < 32; ii++) s += sC[ii * 32 + jj] * Wq[ii * 64 + c];
        sP[e] = s;
    }
    __syncthreads();

    float* Mb = g_M + b * 4096;
    for (int e = tid; e < 4096; e += 256) {
        int o = e >> 6, c = e & 63;
        float s = 0.0f;
        for (int jj = 0; jj < 32; jj++) s += w_out[o * 128 + h * 32 + jj] * sP[jj * 64 + c];
        atomicAdd(&Mb[e], s);
    }
}

// ---------------------------------------------------------------------------
// Pass C: stationary A = [[Mh, Mh],[Ml, 0]] (128x128 bf16 rows o', k=ch hi|lo).
// X tile stored CHANNEL-major: rows k=128 (ch-hi 0-63, ch-lo 64-127), 128 tok,
// stride 272B -> loads are gram-identical float4; B frags via ldmatrix.trans.
//   y[o][t] = D[o][t] + D[o+64][t] = Mh·x + Ml·xh  (error ~ Ml·xl ~4e-6)
// Warp owns 16 tokens; zero block skipped. LN: 3-shfl butterfly; STG.64 .cs.
// smem: A at 0 (34816B), X at 34816 (34816B).
// ---------------------------------------------------------------------------
#define APPLY_SMEM (34816 * 2)

__global__ void __launch_bounds__(256, 2) apply_kernel(const float* __restrict__ x,
                                                       const float* __restrict__ b_out,
                                                       const float* __restrict__ gain,
                                                       float* __restrict__ out) {
    extern __shared__ char smem[];
    const uint32_t sb = smem_u32(smem);
    const int tid = threadIdx.x, wid = tid >> 5, lane = tid & 31;
    const int b = blockIdx.y;
    const float* xb = x + (size_t)b * NCH * N_TOK;
    float* ob = out + (size_t)b * NCH * N_TOK;

    // build stationary A from g_M
    {
        const float* Mb = g_M + b * 4096;
        __nv_bfloat16* pa = reinterpret_cast<__nv_bfloat16*>(smem);
        for (int e = tid; e < 4096; e += 256) {
            int o = e >> 6, c = e & 63;
            float m = Mb[e];
            __nv_bfloat16 h = __float2bfloat16(m);
            __nv_bfloat16 l = __float2bfloat16(m - __bfloat162float(h));
            pa[o * 136 + c]        = h;
            pa[o * 136 + 64 + c]   = h;
            pa[(64 + o) * 136 + c] = l;   // cols 64-127 of bottom never read
        }
    }

    const int row = lane >> 2;
    float bb[4][2], gg[4][2];
#pragma unroll
    for (int m = 0; m < 4; m++)
#pragma unroll
        for (int rh = 0; rh < 2; rh++) {
            int o = 16 * m + row + 8 * rh;
            bb[m][rh] = b_out[o];
            gg[m][rh] = gain[o];
        }

    const int tw = 16 * wid;
    // trans-ldsm lane address: k-row (lane&7)+((lane>>4)<<3), token col tw+((lane>>3)&1)*8
    const uint32_t xTB = sb + 34816 +
        ((lane & 7) + ((lane >> 4) << 3)) * 272 + (tw + ((lane >> 3) & 1) * 8) * 2;
    const uint32_t aBa = sb + (lane & 15) * 272 + ((lane >> 4) & 1) * 16;

    for (int tile = blockIdx.x; tile < N_TOK / 128; tile += gridDim.x) {
        const int base = tile * 128;
        __syncthreads();

        // channel-major tile load (gram-identical)
#pragma unroll
        for (int k = 0; k < 8; k++) {
            int idx = k * 256 + tid;
            int c = idx >> 5, t4 = (idx & 31) << 2;
            float4 v = *reinterpret_cast<const float4*>(xb + (size_t)c * N_TOK + base + t4);
            uint32_t h0, l0, h1, l1;
            split2(v.x, v.y, h0, l0);
            split2(v.z, v.w, h1, l1);
            uint2 hw; hw.x = h0; hw.y = h1;
            uint2 lw; lw.x = l0; lw.y = l1;
            *reinterpret_cast<uint2*>(smem + 34816 + c * 272 + t4 * 2) = hw;
            *reinterpret_cast<uint2*>(smem + 34816 + (64 + c) * 272 + t4 * 2) = lw;
        }
        __syncthreads();

        float d[8][2][4];
#pragma unroll
        for (int m = 0; m < 8; m++)
#pragma unroll
            for (int nn = 0; nn < 2; nn++)
#pragma unroll
                for (int r = 0; r < 4; r++) d[m][nn][r] = 0.0f;

#pragma unroll
        for (int k = 0; k < 8; k++) {
            uint32_t bf[4];
            ldsm4t(bf, xTB + k * 4352);          // k-step = 16 rows * 272B
            const int mm = (k < 4) ? 8 : 4;
#pragma unroll
            for (int m = 0; m < 8; m++) {
                if (m >= mm) break;
                uint32_t af[4];
                ldsm4(af, aBa + m * (16 * 272) + k * 32);
                mma16816(d[m][0], af, bf[0], bf[2]);
                mma16816(d[m][1], af, bf[1], bf[3]);
            }
        }

        // epilogue: fold halves + bias, per-token stats, normalize, store
        float yy[4][2][4];
        float s[2][2] = {{0.f, 0.f}, {0.f, 0.f}};
        float qq[2][2] = {{0.f, 0.f}, {0.f, 0.f}};
#pragma unroll
        for (int m = 0; m < 4; m++)
#pragma unroll
            for (int nn = 0; nn < 2; nn++)
#pragma unroll
                for (int r = 0; r < 4; r++) {
                    float v = d[m][nn][r] + d[m + 4][nn][r] + bb[m][r >> 1];
                    yy[m][nn][r] = v;
                    s[nn][r & 1] += v;
                    qq[nn][r & 1] += v * v;
                }
#pragma unroll
        for (int mask = 4; mask < 32; mask <<= 1)
#pragma unroll
            for (int nn = 0; nn < 2; nn++)
#pragma unroll
                for (int p = 0; p < 2; p++) {
                    s[nn][p]  += __shfl_xor_sync(0xffffffffu, s[nn][p], mask);
                    qq[nn][p] += __shfl_xor_sync(0xffffffffu, qq[nn][p], mask);
                }
        float mean[2][2], istd[2][2];
#pragma unroll
        for (int nn = 0; nn < 2; nn++)
#pragma unroll
            for (int p = 0; p < 2; p++) {
                float mu = s[nn][p] * (1.0f / 64.0f);
                mean[nn][p] = mu;
                istd[nn][p] = rsqrtf(qq[nn][p] * (1.0f / 64.0f) - mu * mu + 1e-5f);
            }

        float* obp = ob + base;
#pragma unroll
        for (int m = 0; m < 4; m++)
#pragma unroll
            for (int nn = 0; nn < 2; nn++) {
                const int o  = 16 * m + row;
                const int tt = tw + 8 * nn + 2 * (lane & 3);
                stcs2(obp + (size_t)o * N_TOK + tt,
                      (yy[m][nn][0] - mean[nn][0]) * istd[nn][0] * gg[m][0],
                      (yy[m][nn][1] - mean[nn][1]) * istd[nn][1] * gg[m][0]);
                stcs2(obp + (size_t)(o + 8) * N_TOK + tt,
                      (yy[m][nn][2] - mean[nn][0]) * istd[nn][0] * gg[m][1],
                      (yy[m][nn][3] - mean[nn][1]) * istd[nn][1] * gg[m][1]);
            }
    }
}

// ---------------------------------------------------------------------------
extern "C" void kernel_launch(void* const* d_in, const int* in_sizes, int n_in,
                              void* d_out, int out_size) {
    const float* x     = (const float*)d_in[0];
    const float* w_qkv = (const float*)d_in[1];
    const float* w_out = (const float*)d_in[2];
    const float* b_out = (const float*)d_in[3];
    const float* g     = (const float*)d_in[4];
    float* out = (float*)d_out;

    cudaFuncSetAttribute(apply_kernel, cudaFuncAttributeMaxDynamicSharedMemorySize, APPLY_SMEM);

    zero_kernel<<<32, 256>>>();
    gram_kernel<<<dim3(148, 2), 256, GRAM_SMEM>>>(x);
    combine_kernel<<<dim3(4, 2), 256>>>(w_qkv, w_out);
    apply_kernel<<<dim3(296, 2), 256, APPLY_SMEM>>>(x, b_out, g, out);
}

// round 7
// speedup vs baseline: 2.1574x; 1.0320x over previous
#include <cuda_runtime.h>
#include <cuda_bf16.h>
#include <cstdint>

#define N_TOK 262144
#define NCH   64

__device__ float g_S[2 * 4096];
__device__ float g_M[2 * 4096];   // M: [o][c], c contiguous

// ---------------------------------------------------------------------------
static __device__ __forceinline__ uint32_t smem_u32(const void* p) {
    uint32_t a;
    asm("{ .reg .u64 t; cvta.to.shared.u64 t, %1; cvt.u32.u64 %0, t; }" : "=r"(a) : "l"(p));
    return a;
}
static __device__ __forceinline__ void ldsm4(uint32_t (&r)[4], uint32_t a) {
    asm volatile("ldmatrix.sync.aligned.m8n8.x4.shared.b16 {%0,%1,%2,%3}, [%4];"
                 : "=r"(r[0]), "=r"(r[1]), "=r"(r[2]), "=r"(r[3]) : "r"(a));
}
static __device__ __forceinline__ void ldsm4t(uint32_t (&r)[4], uint32_t a) {
    asm volatile("ldmatrix.sync.aligned.m8n8.x4.trans.shared.b16 {%0,%1,%2,%3}, [%4];"
                 : "=r"(r[0]), "=r"(r[1]), "=r"(r[2]), "=r"(r[3]) : "r"(a));
}
static __device__ __forceinline__ void mma16816(float (&d)[4], const uint32_t (&a)[4],
                                                uint32_t b0, uint32_t b1) {
    asm volatile("mma.sync.aligned.m16n8k16.row.col.f32.bf16.bf16.f32 "
                 "{%0,%1,%2,%3},{%4,%5,%6,%7},{%8,%9},{%0,%1,%2,%3};"
                 : "+f"(d[0]), "+f"(d[1]), "+f"(d[2]), "+f"(d[3])
                 : "r"(a[0]), "r"(a[1]), "r"(a[2]), "r"(a[3]), "r"(b0), "r"(b1));
}
// packed convert: {lo: bf16(lo), hi: bf16(hi)}
static __device__ __forceinline__ uint32_t cvt2bf(float lo, float hi) {
    uint32_t d;
    asm("cvt.rn.bf16x2.f32 %0,%1,%2;" : "=r"(d) : "f"(hi), "f"(lo));
    return d;
}
// pack top-16-bits of a (lo half) and b (hi half): truncation-split hi parts
static __device__ __forceinline__ uint32_t prmt_hi(float a, float b) {
    uint32_t d;
    asm("prmt.b32 %0,%1,%2,0x7632;" : "=r"(d) : "r"(__float_as_uint(a)), "r"(__float_as_uint(b)));
    return d;
}
static __device__ __forceinline__ float trunc16(float a) {
    return __uint_as_float(__float_as_uint(a) & 0xFFFF0000u);
}
static __device__ __forceinline__ void stcs2(float* p, float a, float b) {
    asm volatile("st.global.cs.v2.f32 [%0], {%1,%2};" :: "l"(p), "f"(a), "f"(b) : "memory");
}

// ---------------------------------------------------------------------------
__global__ void zero_kernel() {
    int i = blockIdx.x * 256 + threadIdx.x;
    if (i < 2 * 4096) { g_S[i] = 0.0f; g_M[i] = 0.0f; }
}

// ---------------------------------------------------------------------------
// Pass A (pure bf16): S = Xh·Xh^T. 256-token tiles; smem [64 ch][256 tok]
// bf16, row stride 528B. Warp = (m-stripe mw, token-half kh); D[16][64] in
// regs across tiles. Epilogue: two smem regions (one per kh), combine, atomic.
// bf16-only error ~1e-5 rel on S's dominant scale (averages over 262k tokens).
// ---------------------------------------------------------------------------
#define GRAM_SMEM 34816

__global__ void __launch_bounds__(256, 2) gram_kernel(const float* __restrict__ x) {
    extern __shared__ char smem[];
    const uint32_t sb = smem_u32(smem);
    const int tid = threadIdx.x, wid = tid >> 5, lane = tid & 31;
    const int b = blockIdx.y;
    const float* xb = x + (size_t)b * NCH * N_TOK;
    const int mw = wid & 3, kh = wid >> 2;

    float d[8][4];
#pragma unroll
    for (int nn = 0; nn < 8; nn++)
#pragma unroll
        for (int r = 0; r < 4; r++) d[nn][r] = 0.0f;

    const uint32_t aAddr = sb + (16 * mw + (lane & 15)) * 528 + ((lane >> 4) & 1) * 16 + kh * 256;
    const uint32_t bBase = sb + (lane & 15) * 528 + ((lane >> 4) & 1) * 16 + kh * 256;

    uint4 w[8];
    int tile = blockIdx.x;
    // prefetch + convert tile 0
#pragma unroll
    for (int j = 0; j < 8; j++) {
        int idx = j * 256 + tid;
        int c = idx >> 5, t8 = (idx & 31) << 3;
        const float* p = xb + (size_t)c * N_TOK + tile * 256 + t8;
        float4 v0 = *reinterpret_cast<const float4*>(p);
        float4 v1 = *reinterpret_cast<const float4*>(p + 4);
        w[j].x = cvt2bf(v0.x, v0.y); w[j].y = cvt2bf(v0.z, v0.w);
        w[j].z = cvt2bf(v1.x, v1.y); w[j].w = cvt2bf(v1.z, v1.w);
    }

    for (; tile < N_TOK / 256; tile += gridDim.x) {
        __syncthreads();
#pragma unroll
        for (int j = 0; j < 8; j++) {
            int idx = j * 256 + tid;
            int c = idx >> 5, t8 = (idx & 31) << 3;
            *reinterpret_cast<uint4*>(smem + c * 528 + t8 * 2) = w[j];
        }
        __syncthreads();

        const int ntile = tile + gridDim.x;
        if (ntile < N_TOK / 256) {
#pragma unroll
            for (int j = 0; j < 8; j++) {
                int idx = j * 256 + tid;
                int c = idx >> 5, t8 = (idx & 31) << 3;
                const float* p = xb + (size_t)c * N_TOK + ntile * 256 + t8;
                float4 v0 = *reinterpret_cast<const float4*>(p);
                float4 v1 = *reinterpret_cast<const float4*>(p + 4);
                w[j].x = cvt2bf(v0.x, v0.y); w[j].y = cvt2bf(v0.z, v0.w);
                w[j].z = cvt2bf(v1.x, v1.y); w[j].w = cvt2bf(v1.z, v1.w);
            }
        }

#pragma unroll
        for (int k = 0; k < 8; k++) {
            uint32_t af[4];
            ldsm4(af, aAddr + k * 32);
#pragma unroll
            for (int nn2 = 0; nn2 < 4; nn2++) {
                uint32_t bf[4];
                ldsm4(bf, bBase + nn2 * (16 * 528) + k * 32);
                mma16816(d[2 * nn2],     af, bf[0], bf[2]);
                mma16816(d[2 * nn2 + 1], af, bf[1], bf[3]);
            }
        }
    }

    // stage D to smem: region kh (float[64][68] each)
    __syncthreads();
    float* sf = reinterpret_cast<float*>(smem) + kh * 4352;
    const int row0 = 16 * mw + (lane >> 2);
    const int col0 = 2 * (lane & 3);
#pragma unroll
    for (int nn = 0; nn < 8; nn++) {
        sf[row0 * 68 + 8 * nn + col0]           = d[nn][0];
        sf[row0 * 68 + 8 * nn + col0 + 1]       = d[nn][1];
        sf[(row0 + 8) * 68 + 8 * nn + col0]     = d[nn][2];
        sf[(row0 + 8) * 68 + 8 * nn + col0 + 1] = d[nn][3];
    }
    __syncthreads();

    float* Sb = g_S + b * 4096;
    float* sf0 = reinterpret_cast<float*>(smem);
#pragma unroll
    for (int kk = 0; kk < 16; kk++) {
        int e = kk * 256 + tid;
        int i = e >> 6, j2 = e & 63;
        atomicAdd(&Sb[e], sf0[i * 68 + j2] + sf0[4352 + i * 68 + j2]);
    }
}

// ---------------------------------------------------------------------------
// Pass B: fold weights into M[o][c]. One block per (head, batch).
// ---------------------------------------------------------------------------
__global__ void __launch_bounds__(256) combine_kernel(const float* __restrict__ w_qkv,
                                                      const float* __restrict__ w_out) {
    __shared__ float sS[4096];
    __shared__ float sA[2048];
    __shared__ float sC[1024];
    __shared__ float sP[2048];
    const int b = blockIdx.y, h = blockIdx.x;
    const int tid = threadIdx.x;

    const float* Sb = g_S + b * 4096;
    for (int k = tid; k < 4096; k += 256) sS[k] = Sb[k];
    __syncthreads();

    const float* Wq = w_qkv + (h * 32) * 64;
    const float* Wk = w_qkv + (128 + h * 32) * 64;
    const float* Wv = w_qkv + (256 + h * 32) * 64;

    for (int e = tid; e < 2048; e += 256) {
        int ii = e >> 6, c = e & 63;
        float s = 0.0f;
        for (int c2 = 0; c2 < 64; c2++) s += Wk[ii * 64 + c2] * sS[c2 * 64 + c];
        sA[e] = s;
    }
    __syncthreads();

    const float coef = 0.17677669529663688f / 4096.0f;
    for (int e = tid; e < 1024; e += 256) {
        int ii = e >> 5, jj = e & 31;
        float s = 0.0f;
        for (int c = 0; c < 64; c++) s += sA[ii * 64 + c] * Wv[jj * 64 + c];
        sC[e] = s * coef;
    }
    __syncthreads();

    for (int e = tid; e < 2048; e += 256) {
        int jj = e >> 6, c = e & 63;
        float s = 0.0f;
        for (int ii = 0; ii < 32; ii++) s += sC[ii * 32 + jj] * Wq[ii * 64 + c];
        sP[e] = s;
    }
    __syncthreads();

    float* Mb = g_M + b * 4096;
    for (int e = tid; e < 4096; e += 256) {
        int o = e >> 6, c = e & 63;
        float s = 0.0f;
        for (int jj = 0; jj < 32; jj++) s += w_out[o * 128 + h * 32 + jj] * sP[jj * 64 + c];
        atomicAdd(&Mb[e], s);
    }
}

// ---------------------------------------------------------------------------
// Pass C: A region = [Mh (rows 0-63); Ml (rows 64-127)], 64 cols, stride 144B.
// X tile channel-major [k=128 rows: xh 0-63, xl 64-127][128 tok], stride 272B.
// k-pair loop: one Mh fragment feeds BOTH xh and xl B-fragments:
//   y[o][t] = Mh·xh + Mh·xl + Ml·xh   (drops Ml·xl ~4e-6)
// Truncation split: hi via PRMT, lo via single cvt.bf16x2; STS.128.
// Warp owns 16 tokens; LN thread-local + 3-shfl butterfly; STG.64 .cs.
// ---------------------------------------------------------------------------
#define XOFF 18432
#define APPLY_SMEM (18432 + 34816)

__global__ void __launch_bounds__(256, 2) apply_kernel(const float* __restrict__ x,
                                                       const float* __restrict__ b_out,
                                                       const float* __restrict__ gain,
                                                       float* __restrict__ out) {
    extern __shared__ char smem[];
    const uint32_t sb = smem_u32(smem);
    const int tid = threadIdx.x, wid = tid >> 5, lane = tid & 31;
    const int b = blockIdx.y;
    const float* xb = x + (size_t)b * NCH * N_TOK;
    float* ob = out + (size_t)b * NCH * N_TOK;

    // build A: Mh rows 0-63, Ml rows 64-127 (64 cols, stride 72 bf16)
    {
        const float* Mb = g_M + b * 4096;
        __nv_bfloat16* pa = reinterpret_cast<__nv_bfloat16*>(smem);
        for (int e = tid; e < 4096; e += 256) {
            int o = e >> 6, c = e & 63;
            float m = Mb[e];
            __nv_bfloat16 h = __float2bfloat16(m);
            __nv_bfloat16 l = __float2bfloat16(m - __bfloat162float(h));
            pa[o * 72 + c]        = h;
            pa[(64 + o) * 72 + c] = l;
        }
    }

    const int row = lane >> 2;
    float bb[4][2], gg[4][2];
#pragma unroll
    for (int m = 0; m < 4; m++)
#pragma unroll
        for (int rh = 0; rh < 2; rh++) {
            int o = 16 * m + row + 8 * rh;
            bb[m][rh] = b_out[o];
            gg[m][rh] = gain[o];
        }

    const int tw = 16 * wid;
    const uint32_t xTB = sb + XOFF +
        ((lane & 7) + ((lane >> 4) << 3)) * 272 + (tw + ((lane >> 3) & 1) * 8) * 2;
    const uint32_t aBa = sb + (lane & 15) * 144 + ((lane >> 4) & 1) * 16;

    for (int tile = blockIdx.x; tile < N_TOK / 128; tile += gridDim.x) {
        const int base = tile * 128;
        __syncthreads();

        // channel-major tile: thread loads 8 consecutive tokens x 4 channels
#pragma unroll
        for (int j = 0; j < 4; j++) {
            int idx = j * 256 + tid;
            int c = idx >> 4, t8 = (idx & 15) << 3;
            const float* p = xb + (size_t)c * N_TOK + base + t8;
            float4 v0 = *reinterpret_cast<const float4*>(p);
            float4 v1 = *reinterpret_cast<const float4*>(p + 4);
            uint4 hw, lw;
            hw.x = prmt_hi(v0.x, v0.y); hw.y = prmt_hi(v0.z, v0.w);
            hw.z = prmt_hi(v1.x, v1.y); hw.w = prmt_hi(v1.z, v1.w);
            lw.x = cvt2bf(v0.x - trunc16(v0.x), v0.y - trunc16(v0.y));
            lw.y = cvt2bf(v0.z - trunc16(v0.z), v0.w - trunc16(v0.w));
            lw.z = cvt2bf(v1.x - trunc16(v1.x), v1.y - trunc16(v1.y));
            lw.w = cvt2bf(v1.z - trunc16(v1.z), v1.w - trunc16(v1.w));
            *reinterpret_cast<uint4*>(smem + XOFF + c * 272 + t8 * 2)        = hw;
            *reinterpret_cast<uint4*>(smem + XOFF + (64 + c) * 272 + t8 * 2) = lw;
        }
        __syncthreads();

        float d[8][2][4];
#pragma unroll
        for (int m = 0; m < 8; m++)
#pragma unroll
            for (int nn = 0; nn < 2; nn++)
#pragma unroll
                for (int r = 0; r < 4; r++) d[m][nn][r] = 0.0f;

#pragma unroll
        for (int kp = 0; kp < 4; kp++) {
            uint32_t bh[4], bl[4];
            ldsm4t(bh, xTB + kp * 4352);
            ldsm4t(bl, xTB + 64 * 272 + kp * 4352);
#pragma unroll
            for (int m = 0; m < 4; m++) {
                uint32_t af[4];
                ldsm4(af, aBa + m * 2304 + kp * 32);
                mma16816(d[m][0], af, bh[0], bh[2]);
                mma16816(d[m][1], af, bh[1], bh[3]);
                mma16816(d[m][0], af, bl[0], bl[2]);
                mma16816(d[m][1], af, bl[1], bl[3]);
            }
#pragma unroll
            for (int m = 0; m < 4; m++) {
                uint32_t af[4];
                ldsm4(af, aBa + (4 + m) * 2304 + kp * 32);
                mma16816(d[4 + m][0], af, bh[0], bh[2]);
                mma16816(d[4 + m][1], af, bh[1], bh[3]);
            }
        }

        // epilogue: fold halves + bias, per-token stats, normalize, store
        float yy[4][2][4];
        float s[2][2] = {{0.f, 0.f}, {0.f, 0.f}};
        float qq[2][2] = {{0.f, 0.f}, {0.f, 0.f}};
#pragma unroll
        for (int m = 0; m < 4; m++)
#pragma unroll
            for (int nn = 0; nn < 2; nn++)
#pragma unroll
                for (int r = 0; r < 4; r++) {
                    float v = d[m][nn][r] + d[m + 4][nn][r] + bb[m][r >> 1];
                    yy[m][nn][r] = v;
                    s[nn][r & 1] += v;
                    qq[nn][r & 1] += v * v;
                }
#pragma unroll
        for (int mask = 4; mask < 32; mask <<= 1)
#pragma unroll
            for (int nn = 0; nn < 2; nn++)
#pragma unroll
                for (int p = 0; p < 2; p++) {
                    s[nn][p]  += __shfl_xor_sync(0xffffffffu, s[nn][p], mask);
                    qq[nn][p] += __shfl_xor_sync(0xffffffffu, qq[nn][p], mask);
                }
        float mean[2][2], istd[2][2];
#pragma unroll
        for (int nn = 0; nn < 2; nn++)
#pragma unroll
            for (int p = 0; p < 2; p++) {
                float mu = s[nn][p] * (1.0f / 64.0f);
                mean[nn][p] = mu;
                istd[nn][p] = rsqrtf(qq[nn][p] * (1.0f / 64.0f) - mu * mu + 1e-5f);
            }

        float* obp = ob + base;
#pragma unroll
        for (int m = 0; m < 4; m++)
#pragma unroll
            for (int nn = 0; nn < 2; nn++) {
                const int o  = 16 * m + row;
                const int tt = tw + 8 * nn + 2 * (lane & 3);
                stcs2(obp + (size_t)o * N_TOK + tt,
                      (yy[m][nn][0] - mean[nn][0]) * istd[nn][0] * gg[m][0],
                      (yy[m][nn][1] - mean[nn][1]) * istd[nn][1] * gg[m][0]);
                stcs2(obp + (size_t)(o + 8) * N_TOK + tt,
                      (yy[m][nn][2] - mean[nn][0]) * istd[nn][0] * gg[m][1],
                      (yy[m][nn][3] - mean[nn][1]) * istd[nn][1] * gg[m][1]);
            }
    }
}

// ---------------------------------------------------------------------------
extern "C" void kernel_launch(void* const* d_in, const int* in_sizes, int n_in,
                              void* d_out, int out_size) {
    const float* x     = (const float*)d_in[0];
    const float* w_qkv = (const float*)d_in[1];
    const float* w_out = (const float*)d_in[2];
    const float* b_out = (const float*)d_in[3];
    const float* g     = (const float*)d_in[4];
    float* out = (float*)d_out;

    cudaFuncSetAttribute(apply_kernel, cudaFuncAttributeMaxDynamicSharedMemorySize, APPLY_SMEM);

    zero_kernel<<<32, 256>>>();
    gram_kernel<<<dim3(148, 2), 256, GRAM_SMEM>>>(x);
    combine_kernel<<<dim3(4, 2), 256>>>(w_qkv, w_out);
    apply_kernel<<<dim3(296, 2), 256, APPLY_SMEM>>>(x, b_out, g, out);
}

// round 8
// speedup vs baseline: 2.2730x; 1.0536x over previous
#include <cuda_runtime.h>
#include <cuda_bf16.h>
#include <cstdint>

#define N_TOK 262144
#define NCH   64

__device__ float g_S[2 * 4096];
__device__ float g_M[2 * 4096];   // M: [o][c], c contiguous

// ---------------------------------------------------------------------------
static __device__ __forceinline__ uint32_t smem_u32(const void* p) {
    uint32_t a;
    asm("{ .reg .u64 t; cvta.to.shared.u64 t, %1; cvt.u32.u64 %0, t; }" : "=r"(a) : "l"(p));
    return a;
}
static __device__ __forceinline__ void ldsm4(uint32_t (&r)[4], uint32_t a) {
    asm volatile("ldmatrix.sync.aligned.m8n8.x4.shared.b16 {%0,%1,%2,%3}, [%4];"
                 : "=r"(r[0]), "=r"(r[1]), "=r"(r[2]), "=r"(r[3]) : "r"(a));
}
static __device__ __forceinline__ void ldsm4t(uint32_t (&r)[4], uint32_t a) {
    asm volatile("ldmatrix.sync.aligned.m8n8.x4.trans.shared.b16 {%0,%1,%2,%3}, [%4];"
                 : "=r"(r[0]), "=r"(r[1]), "=r"(r[2]), "=r"(r[3]) : "r"(a));
}
static __device__ __forceinline__ void mma16816(float (&d)[4], const uint32_t (&a)[4],
                                                uint32_t b0, uint32_t b1) {
    asm volatile("mma.sync.aligned.m16n8k16.row.col.f32.bf16.bf16.f32 "
                 "{%0,%1,%2,%3},{%4,%5,%6,%7},{%8,%9},{%0,%1,%2,%3};"
                 : "+f"(d[0]), "+f"(d[1]), "+f"(d[2]), "+f"(d[3])
                 : "r"(a[0]), "r"(a[1]), "r"(a[2]), "r"(a[3]), "r"(b0), "r"(b1));
}
// packed convert: {lo: bf16(lo), hi: bf16(hi)}
static __device__ __forceinline__ uint32_t cvt2bf(float lo, float hi) {
    uint32_t d;
    asm("cvt.rn.bf16x2.f32 %0,%1,%2;" : "=r"(d) : "f"(hi), "f"(lo));
    return d;
}
// pack top-16-bits of a (lo half) and b (hi half): truncation-split hi parts
static __device__ __forceinline__ uint32_t prmt_hi(float a, float b) {
    uint32_t d;
    asm("prmt.b32 %0,%1,%2,0x7632;" : "=r"(d) : "r"(__float_as_uint(a)), "r"(__float_as_uint(b)));
    return d;
}
static __device__ __forceinline__ float trunc16(float a) {
    return __uint_as_float(__float_as_uint(a) & 0xFFFF0000u);
}
static __device__ __forceinline__ void stcs2(float* p, float a, float b) {
    asm volatile("st.global.cs.v2.f32 [%0], {%1,%2};" :: "l"(p), "f"(a), "f"(b) : "memory");
}

// ---------------------------------------------------------------------------
__global__ void zero_kernel() {
    int i = blockIdx.x * 256 + threadIdx.x;
    if (i < 2 * 4096) { g_S[i] = 0.0f; g_M[i] = 0.0f; }
}

// ---------------------------------------------------------------------------
// Pass A (pure bf16): S = Xh·Xh^T. 256-token tiles; smem [64 ch][256 tok]
// bf16, row stride 528B. Warp = (m-stripe mw, token-half kh); D[16][64] in
// regs across tiles. Prefetched+converted next tile held in registers.
// ---------------------------------------------------------------------------
#define GRAM_SMEM 34816

__global__ void __launch_bounds__(256, 2) gram_kernel(const float* __restrict__ x) {
    extern __shared__ char smem[];
    const uint32_t sb = smem_u32(smem);
    const int tid = threadIdx.x, wid = tid >> 5, lane = tid & 31;
    const int b = blockIdx.y;
    const float* xb = x + (size_t)b * NCH * N_TOK;
    const int mw = wid & 3, kh = wid >> 2;

    float d[8][4];
#pragma unroll
    for (int nn = 0; nn < 8; nn++)
#pragma unroll
        for (int r = 0; r < 4; r++) d[nn][r] = 0.0f;

    const uint32_t aAddr = sb + (16 * mw + (lane & 15)) * 528 + ((lane >> 4) & 1) * 16 + kh * 256;
    const uint32_t bBase = sb + (lane & 15) * 528 + ((lane >> 4) & 1) * 16 + kh * 256;

    uint4 w[8];
    int tile = blockIdx.x;
#pragma unroll
    for (int j = 0; j < 8; j++) {
        int idx = j * 256 + tid;
        int c = idx >> 5, t8 = (idx & 31) << 3;
        const float* p = xb + (size_t)c * N_TOK + tile * 256 + t8;
        float4 v0 = *reinterpret_cast<const float4*>(p);
        float4 v1 = *reinterpret_cast<const float4*>(p + 4);
        w[j].x = cvt2bf(v0.x, v0.y); w[j].y = cvt2bf(v0.z, v0.w);
        w[j].z = cvt2bf(v1.x, v1.y); w[j].w = cvt2bf(v1.z, v1.w);
    }

    for (; tile < N_TOK / 256; tile += gridDim.x) {
        __syncthreads();
#pragma unroll
        for (int j = 0; j < 8; j++) {
            int idx = j * 256 + tid;
            int c = idx >> 5, t8 = (idx & 31) << 3;
            *reinterpret_cast<uint4*>(smem + c * 528 + t8 * 2) = w[j];
        }
        __syncthreads();

        const int ntile = tile + gridDim.x;
        if (ntile < N_TOK / 256) {
#pragma unroll
            for (int j = 0; j < 8; j++) {
                int idx = j * 256 + tid;
                int c = idx >> 5, t8 = (idx & 31) << 3;
                const float* p = xb + (size_t)c * N_TOK + ntile * 256 + t8;
                float4 v0 = *reinterpret_cast<const float4*>(p);
                float4 v1 = *reinterpret_cast<const float4*>(p + 4);
                w[j].x = cvt2bf(v0.x, v0.y); w[j].y = cvt2bf(v0.z, v0.w);
                w[j].z = cvt2bf(v1.x, v1.y); w[j].w = cvt2bf(v1.z, v1.w);
            }
        }

#pragma unroll
        for (int k = 0; k < 8; k++) {
            uint32_t af[4];
            ldsm4(af, aAddr + k * 32);
#pragma unroll
            for (int nn2 = 0; nn2 < 4; nn2++) {
                uint32_t bf[4];
                ldsm4(bf, bBase + nn2 * (16 * 528) + k * 32);
                mma16816(d[2 * nn2],     af, bf[0], bf[2]);
                mma16816(d[2 * nn2 + 1], af, bf[1], bf[3]);
            }
        }
    }

    // stage D to smem: region kh (float[64][68] each)
    __syncthreads();
    float* sf = reinterpret_cast<float*>(smem) + kh * 4352;
    const int row0 = 16 * mw + (lane >> 2);
    const int col0 = 2 * (lane & 3);
#pragma unroll
    for (int nn = 0; nn < 8; nn++) {
        sf[row0 * 68 + 8 * nn + col0]           = d[nn][0];
        sf[row0 * 68 + 8 * nn + col0 + 1]       = d[nn][1];
        sf[(row0 + 8) * 68 + 8 * nn + col0]     = d[nn][2];
        sf[(row0 + 8) * 68 + 8 * nn + col0 + 1] = d[nn][3];
    }
    __syncthreads();

    float* Sb = g_S + b * 4096;
    float* sf0 = reinterpret_cast<float*>(smem);
#pragma unroll
    for (int kk = 0; kk < 16; kk++) {
        int e = kk * 256 + tid;
        int i = e >> 6, j2 = e & 63;
        atomicAdd(&Sb[e], sf0[i * 68 + j2] + sf0[4352 + i * 68 + j2]);
    }
}

// ---------------------------------------------------------------------------
// Pass B: fold weights into M[o][c]. One block per (head, batch).
// ---------------------------------------------------------------------------
__global__ void __launch_bounds__(256) combine_kernel(const float* __restrict__ w_qkv,
                                                      const float* __restrict__ w_out) {
    __shared__ float sS[4096];
    __shared__ float sA[2048];
    __shared__ float sC[1024];
    __shared__ float sP[2048];
    const int b = blockIdx.y, h = blockIdx.x;
    const int tid = threadIdx.x;

    const float* Sb = g_S + b * 4096;
    for (int k = tid; k < 4096; k += 256) sS[k] = Sb[k];
    __syncthreads();

    const float* Wq = w_qkv + (h * 32) * 64;
    const float* Wk = w_qkv + (128 + h * 32) * 64;
    const float* Wv = w_qkv + (256 + h * 32) * 64;

    for (int e = tid; e < 2048; e += 256) {
        int ii = e >> 6, c = e & 63;
        float s = 0.0f;
        for (int c2 = 0; c2 < 64; c2++) s += Wk[ii * 64 + c2] * sS[c2 * 64 + c];
        sA[e] = s;
    }
    __syncthreads();

    const float coef = 0.17677669529663688f / 4096.0f;
    for (int e = tid; e < 1024; e += 256) {
        int ii = e >> 5, jj = e & 31;
        float s = 0.0f;
        for (int c = 0; c < 64; c++) s += sA[ii * 64 + c] * Wv[jj * 64 + c];
        sC[e] = s * coef;
    }
    __syncthreads();

    for (int e = tid; e < 2048; e += 256) {
        int jj = e >> 6, c = e & 63;
        float s = 0.0f;
        for (int ii = 0; ii < 32; ii++) s += sC[ii * 32 + jj] * Wq[ii * 64 + c];
        sP[e] = s;
    }
    __syncthreads();

    float* Mb = g_M + b * 4096;
    for (int e = tid; e < 4096; e += 256) {
        int o = e >> 6, c = e & 63;
        float s = 0.0f;
        for (int jj = 0; jj < 32; jj++) s += w_out[o * 128 + h * 32 + jj] * sP[jj * 64 + c];
        atomicAdd(&Mb[e], s);
    }
}

// ---------------------------------------------------------------------------
// Pass C: A = [Mh (rows 0-63); Ml (rows 64-127)], 64 cols, stride 144B.
// X tile channel-major [k=128: xh 0-63, xl 64-127][128 tok], stride 272B.
// All three products (Mh·xh, Mh·xl, Ml·xh) accumulate into the SAME d[m]
// registers (32 accs). Next tile's LDGs prefetched into regs during mma.
// Warp owns 16 tokens; LN thread-local + 3-shfl butterfly; STG.64 .cs.
// ---------------------------------------------------------------------------
#define XOFF 18432
#define APPLY_SMEM (18432 + 34816)

__global__ void __launch_bounds__(256, 2) apply_kernel(const float* __restrict__ x,
                                                       const float* __restrict__ b_out,
                                                       const float* __restrict__ gain,
                                                       float* __restrict__ out) {
    extern __shared__ char smem[];
    const uint32_t sb = smem_u32(smem);
    const int tid = threadIdx.x, wid = tid >> 5, lane = tid & 31;
    const int b = blockIdx.y;
    const float* xb = x + (size_t)b * NCH * N_TOK;
    float* ob = out + (size_t)b * NCH * N_TOK;

    // build A: Mh rows 0-63, Ml rows 64-127 (64 cols, stride 72 bf16)
    {
        const float* Mb = g_M + b * 4096;
        __nv_bfloat16* pa = reinterpret_cast<__nv_bfloat16*>(smem);
        for (int e = tid; e < 4096; e += 256) {
            int o = e >> 6, c = e & 63;
            float m = Mb[e];
            __nv_bfloat16 h = __float2bfloat16(m);
            __nv_bfloat16 l = __float2bfloat16(m - __bfloat162float(h));
            pa[o * 72 + c]        = h;
            pa[(64 + o) * 72 + c] = l;
        }
    }

    const int row = lane >> 2;
    float bb[4][2], gg[4][2];
#pragma unroll
    for (int m = 0; m < 4; m++)
#pragma unroll
        for (int rh = 0; rh < 2; rh++) {
            int o = 16 * m + row + 8 * rh;
            bb[m][rh] = b_out[o];
            gg[m][rh] = gain[o];
        }

    const int tw = 16 * wid;
    const uint32_t xTB = sb + XOFF +
        ((lane & 7) + ((lane >> 4) << 3)) * 272 + (tw + ((lane >> 3) & 1) * 8) * 2;
    const uint32_t aBa = sb + (lane & 15) * 144 + ((lane >> 4) & 1) * 16;

    // prefetch first tile
    float4 v[8];
    int tile = blockIdx.x;
#pragma unroll
    for (int j = 0; j < 4; j++) {
        int idx = j * 256 + tid;
        int c = idx >> 4, t8 = (idx & 15) << 3;
        const float* p = xb + (size_t)c * N_TOK + tile * 128 + t8;
        v[2 * j]     = *reinterpret_cast<const float4*>(p);
        v[2 * j + 1] = *reinterpret_cast<const float4*>(p + 4);
    }

    for (; tile < N_TOK / 128; tile += gridDim.x) {
        __syncthreads();
        // convert + store prefetched tile (hi via PRMT, lo via cvt.bf16x2)
#pragma unroll
        for (int j = 0; j < 4; j++) {
            int idx = j * 256 + tid;
            int c = idx >> 4, t8 = (idx & 15) << 3;
            float4 v0 = v[2 * j], v1 = v[2 * j + 1];
            uint4 hw, lw;
            hw.x = prmt_hi(v0.x, v0.y); hw.y = prmt_hi(v0.z, v0.w);
            hw.z = prmt_hi(v1.x, v1.y); hw.w = prmt_hi(v1.z, v1.w);
            lw.x = cvt2bf(v0.x - trunc16(v0.x), v0.y - trunc16(v0.y));
            lw.y = cvt2bf(v0.z - trunc16(v0.z), v0.w - trunc16(v0.w));
            lw.z = cvt2bf(v1.x - trunc16(v1.x), v1.y - trunc16(v1.y));
            lw.w = cvt2bf(v1.z - trunc16(v1.z), v1.w - trunc16(v1.w));
            *reinterpret_cast<uint4*>(smem + XOFF + c * 272 + t8 * 2)        = hw;
            *reinterpret_cast<uint4*>(smem + XOFF + (64 + c) * 272 + t8 * 2) = lw;
        }
        __syncthreads();

        // prefetch next tile's raw fp32 (overlaps with mma + epilogue)
        const int ntile = tile + gridDim.x;
        if (ntile < N_TOK / 128) {
#pragma unroll
            for (int j = 0; j < 4; j++) {
                int idx = j * 256 + tid;
                int c = idx >> 4, t8 = (idx & 15) << 3;
                const float* p = xb + (size_t)c * N_TOK + ntile * 128 + t8;
                v[2 * j]     = *reinterpret_cast<const float4*>(p);
                v[2 * j + 1] = *reinterpret_cast<const float4*>(p + 4);
            }
        }

        float d[4][2][4];
#pragma unroll
        for (int m = 0; m < 4; m++)
#pragma unroll
            for (int nn = 0; nn < 2; nn++)
#pragma unroll
                for (int r = 0; r < 4; r++) d[m][nn][r] = 0.0f;

#pragma unroll
        for (int kp = 0; kp < 4; kp++) {
            uint32_t bh[4], bl[4];
            ldsm4t(bh, xTB + kp * 4352);
            ldsm4t(bl, xTB + 64 * 272 + kp * 4352);
#pragma unroll
            for (int m = 0; m < 4; m++) {
                uint32_t afh[4], afl[4];
                ldsm4(afh, aBa + m * 2304 + kp * 32);
                mma16816(d[m][0], afh, bh[0], bh[2]);
                mma16816(d[m][1], afh, bh[1], bh[3]);
                mma16816(d[m][0], afh, bl[0], bl[2]);
                mma16816(d[m][1], afh, bl[1], bl[3]);
                ldsm4(afl, aBa + (4 + m) * 2304 + kp * 32);
                mma16816(d[m][0], afl, bh[0], bh[2]);
                mma16816(d[m][1], afl, bh[1], bh[3]);
            }
        }

        // epilogue: bias, per-token stats, normalize, store
        float yy[4][2][4];
        float s[2][2] = {{0.f, 0.f}, {0.f, 0.f}};
        float qq[2][2] = {{0.f, 0.f}, {0.f, 0.f}};
#pragma unroll
        for (int m = 0; m < 4; m++)
#pragma unroll
            for (int nn = 0; nn < 2; nn++)
#pragma unroll
                for (int r = 0; r < 4; r++) {
                    float vv = d[m][nn][r] + bb[m][r >> 1];
                    yy[m][nn][r] = vv;
                    s[nn][r & 1] += vv;
                    qq[nn][r & 1] += vv * vv;
                }
#pragma unroll
        for (int mask = 4; mask < 32; mask <<= 1)
#pragma unroll
            for (int nn = 0; nn < 2; nn++)
#pragma unroll
                for (int p = 0; p < 2; p++) {
                    s[nn][p]  += __shfl_xor_sync(0xffffffffu, s[nn][p], mask);
                    qq[nn][p] += __shfl_xor_sync(0xffffffffu, qq[nn][p], mask);
                }
        float mean[2][2], istd[2][2];
#pragma unroll
        for (int nn = 0; nn < 2; nn++)
#pragma unroll
            for (int p = 0; p < 2; p++) {
                float mu = s[nn][p] * (1.0f / 64.0f);
                mean[nn][p] = mu;
                istd[nn][p] = rsqrtf(qq[nn][p] * (1.0f / 64.0f) - mu * mu + 1e-5f);
            }

        float* obp = ob + (size_t)tile * 128;
#pragma unroll
        for (int m = 0; m < 4; m++)
#pragma unroll
            for (int nn = 0; nn < 2; nn++) {
                const int o  = 16 * m + row;
                const int tt = tw + 8 * nn + 2 * (lane & 3);
                stcs2(obp + (size_t)o * N_TOK + tt,
                      (yy[m][nn][0] - mean[nn][0]) * istd[nn][0] * gg[m][0],
                      (yy[m][nn][1] - mean[nn][1]) * istd[nn][1] * gg[m][0]);
                stcs2(obp + (size_t)(o + 8) * N_TOK + tt,
                      (yy[m][nn][2] - mean[nn][0]) * istd[nn][0] * gg[m][1],
                      (yy[m][nn][3] - mean[nn][1]) * istd[nn][1] * gg[m][1]);
            }
    }
}

// ---------------------------------------------------------------------------
extern "C" void kernel_launch(void* const* d_in, const int* in_sizes, int n_in,
                              void* d_out, int out_size) {
    const float* x     = (const float*)d_in[0];
    const float* w_qkv = (const float*)d_in[1];
    const float* w_out = (const float*)d_in[2];
    const float* b_out = (const float*)d_in[3];
    const float* g     = (const float*)d_in[4];
    float* out = (float*)d_out;

    cudaFuncSetAttribute(apply_kernel, cudaFuncAttributeMaxDynamicSharedMemorySize, APPLY_SMEM);

    zero_kernel<<<32, 256>>>();
    gram_kernel<<<dim3(148, 2), 256, GRAM_SMEM>>>(x);
    combine_kernel<<<dim3(4, 2), 256>>>(w_qkv, w_out);
    apply_kernel<<<dim3(296, 2), 256, APPLY_SMEM>>>(x, b_out, g, out);
}

// round 9
// speedup vs baseline: 2.4885x; 1.0948x over previous
#include <cuda_runtime.h>
#include <cuda_fp16.h>
#include <cstdint>

#define N_TOK 262144
#define NCH   64

__device__ float g_S[2 * 4096];
__device__ float g_M[2 * 4096];   // M: [o][c], c contiguous

// ---------------------------------------------------------------------------
static __device__ __forceinline__ uint32_t smem_u32(const void* p) {
    uint32_t a;
    asm("{ .reg .u64 t; cvta.to.shared.u64 t, %1; cvt.u32.u64 %0, t; }" : "=r"(a) : "l"(p));
    return a;
}
static __device__ __forceinline__ void ldsm4(uint32_t (&r)[4], uint32_t a) {
    asm volatile("ldmatrix.sync.aligned.m8n8.x4.shared.b16 {%0,%1,%2,%3}, [%4];"
                 : "=r"(r[0]), "=r"(r[1]), "=r"(r[2]), "=r"(r[3]) : "r"(a));
}
static __device__ __forceinline__ void ldsm4t(uint32_t (&r)[4], uint32_t a) {
    asm volatile("ldmatrix.sync.aligned.m8n8.x4.trans.shared.b16 {%0,%1,%2,%3}, [%4];"
                 : "=r"(r[0]), "=r"(r[1]), "=r"(r[2]), "=r"(r[3]) : "r"(a));
}
static __device__ __forceinline__ void mma16816(float (&d)[4], const uint32_t (&a)[4],
                                                uint32_t b0, uint32_t b1) {
    asm volatile("mma.sync.aligned.m16n8k16.row.col.f32.f16.f16.f32 "
                 "{%0,%1,%2,%3},{%4,%5,%6,%7},{%8,%9},{%0,%1,%2,%3};"
                 : "+f"(d[0]), "+f"(d[1]), "+f"(d[2]), "+f"(d[3])
                 : "r"(a[0]), "r"(a[1]), "r"(a[2]), "r"(a[3]), "r"(b0), "r"(b1));
}
// packed convert: {lo half: f16(lo), hi half: f16(hi)}
static __device__ __forceinline__ uint32_t cvt2h(float lo, float hi) {
    uint32_t d;
    asm("cvt.rn.f16x2.f32 %0,%1,%2;" : "=r"(d) : "f"(hi), "f"(lo));
    return d;
}
static __device__ __forceinline__ void stcs2(float* p, float a, float b) {
    asm volatile("st.global.cs.v2.f32 [%0], {%1,%2};" :: "l"(p), "f"(a), "f"(b) : "memory");
}

// ---------------------------------------------------------------------------
__global__ void zero_kernel() {
    int i = blockIdx.x * 256 + threadIdx.x;
    if (i < 2 * 4096) { g_S[i] = 0.0f; g_M[i] = 0.0f; }
}

// ---------------------------------------------------------------------------
// Pass A (fp16): S = X16·X16^T. 256-token tiles; smem [64 ch][256 tok] f16,
// row stride 528B. Warp = (m-stripe mw, token-half kh); D[16][64] in regs
// across tiles. Next tile prefetched+converted in registers.
// ---------------------------------------------------------------------------
#define GRAM_SMEM 34816

__global__ void __launch_bounds__(256, 2) gram_kernel(const float* __restrict__ x) {
    extern __shared__ char smem[];
    const uint32_t sb = smem_u32(smem);
    const int tid = threadIdx.x, wid = tid >> 5, lane = tid & 31;
    const int b = blockIdx.y;
    const float* xb = x + (size_t)b * NCH * N_TOK;
    const int mw = wid & 3, kh = wid >> 2;

    float d[8][4];
#pragma unroll
    for (int nn = 0; nn < 8; nn++)
#pragma unroll
        for (int r = 0; r < 4; r++) d[nn][r] = 0.0f;

    const uint32_t aAddr = sb + (16 * mw + (lane & 15)) * 528 + ((lane >> 4) & 1) * 16 + kh * 256;
    const uint32_t bBase = sb + (lane & 15) * 528 + ((lane >> 4) & 1) * 16 + kh * 256;

    uint4 w[8];
    int tile = blockIdx.x;
#pragma unroll
    for (int j = 0; j < 8; j++) {
        int idx = j * 256 + tid;
        int c = idx >> 5, t8 = (idx & 31) << 3;
        const float* p = xb + (size_t)c * N_TOK + tile * 256 + t8;
        float4 v0 = *reinterpret_cast<const float4*>(p);
        float4 v1 = *reinterpret_cast<const float4*>(p + 4);
        w[j].x = cvt2h(v0.x, v0.y); w[j].y = cvt2h(v0.z, v0.w);
        w[j].z = cvt2h(v1.x, v1.y); w[j].w = cvt2h(v1.z, v1.w);
    }

    for (; tile < N_TOK / 256; tile += gridDim.x) {
        __syncthreads();
#pragma unroll
        for (int j = 0; j < 8; j++) {
            int idx = j * 256 + tid;
            int c = idx >> 5, t8 = (idx & 31) << 3;
            *reinterpret_cast<uint4*>(smem + c * 528 + t8 * 2) = w[j];
        }
        __syncthreads();

        const int ntile = tile + gridDim.x;
        if (ntile < N_TOK / 256) {
#pragma unroll
            for (int j = 0; j < 8; j++) {
                int idx = j * 256 + tid;
                int c = idx >> 5, t8 = (idx & 31) << 3;
                const float* p = xb + (size_t)c * N_TOK + ntile * 256 + t8;
                float4 v0 = *reinterpret_cast<const float4*>(p);
                float4 v1 = *reinterpret_cast<const float4*>(p + 4);
                w[j].x = cvt2h(v0.x, v0.y); w[j].y = cvt2h(v0.z, v0.w);
                w[j].z = cvt2h(v1.x, v1.y); w[j].w = cvt2h(v1.z, v1.w);
            }
        }

#pragma unroll
        for (int k = 0; k < 8; k++) {
            uint32_t af[4];
            ldsm4(af, aAddr + k * 32);
#pragma unroll
            for (int nn2 = 0; nn2 < 4; nn2++) {
                uint32_t bf[4];
                ldsm4(bf, bBase + nn2 * (16 * 528) + k * 32);
                mma16816(d[2 * nn2],     af, bf[0], bf[2]);
                mma16816(d[2 * nn2 + 1], af, bf[1], bf[3]);
            }
        }
    }

    // stage D to smem: region kh (float[64][68] each)
    __syncthreads();
    float* sf = reinterpret_cast<float*>(smem) + kh * 4352;
    const int row0 = 16 * mw + (lane >> 2);
    const int col0 = 2 * (lane & 3);
#pragma unroll
    for (int nn = 0; nn < 8; nn++) {
        sf[row0 * 68 + 8 * nn + col0]           = d[nn][0];
        sf[row0 * 68 + 8 * nn + col0 + 1]       = d[nn][1];
        sf[(row0 + 8) * 68 + 8 * nn + col0]     = d[nn][2];
        sf[(row0 + 8) * 68 + 8 * nn + col0 + 1] = d[nn][3];
    }
    __syncthreads();

    float* Sb = g_S + b * 4096;
    float* sf0 = reinterpret_cast<float*>(smem);
#pragma unroll
    for (int kk = 0; kk < 16; kk++) {
        int e = kk * 256 + tid;
        int i = e >> 6, j2 = e & 63;
        atomicAdd(&Sb[e], sf0[i * 68 + j2] + sf0[4352 + i * 68 + j2]);
    }
}

// ---------------------------------------------------------------------------
// Pass B: fold weights into M[o][c]. One block per (head, batch).
// ---------------------------------------------------------------------------
__global__ void __launch_bounds__(256) combine_kernel(const float* __restrict__ w_qkv,
                                                      const float* __restrict__ w_out) {
    __shared__ float sS[4096];
    __shared__ float sA[2048];
    __shared__ float sC[1024];
    __shared__ float sP[2048];
    const int b = blockIdx.y, h = blockIdx.x;
    const int tid = threadIdx.x;

    const float* Sb = g_S + b * 4096;
    for (int k = tid; k < 4096; k += 256) sS[k] = Sb[k];
    __syncthreads();

    const float* Wq = w_qkv + (h * 32) * 64;
    const float* Wk = w_qkv + (128 + h * 32) * 64;
    const float* Wv = w_qkv + (256 + h * 32) * 64;

    for (int e = tid; e < 2048; e += 256) {
        int ii = e >> 6, c = e & 63;
        float s = 0.0f;
        for (int c2 = 0; c2 < 64; c2++) s += Wk[ii * 64 + c2] * sS[c2 * 64 + c];
        sA[e] = s;
    }
    __syncthreads();

    const float coef = 0.17677669529663688f / 4096.0f;
    for (int e = tid; e < 1024; e += 256) {
        int ii = e >> 5, jj = e & 31;
        float s = 0.0f;
        for (int c = 0; c < 64; c++) s += sA[ii * 64 + c] * Wv[jj * 64 + c];
        sC[e] = s * coef;
    }
    __syncthreads();

    for (int e = tid; e < 2048; e += 256) {
        int jj = e >> 6, c = e & 63;
        float s = 0.0f;
        for (int ii = 0; ii < 32; ii++) s += sC[ii * 32 + jj] * Wq[ii * 64 + c];
        sP[e] = s;
    }
    __syncthreads();

    float* Mb = g_M + b * 4096;
    for (int e = tid; e < 4096; e += 256) {
        int o = e >> 6, c = e & 63;
        float s = 0.0f;
        for (int jj = 0; jj < 32; jj++) s += w_out[o * 128 + h * 32 + jj] * sP[jj * 64 + c];
        atomicAdd(&Mb[e], s);
    }
}

// ---------------------------------------------------------------------------
// Pass C (fp16 single product): y = M16 · x16.
// A = M [64 rows o][64 cols c] f16, stride 144B.
// X tile channel-major [64 ch][128 tok] f16, stride 272B; B via ldmatrix.trans.
// Warp owns 16 tokens, all 64 channels -> LN thread-local + 3-shfl butterfly.
// Next tile's fp32 LDGs prefetched into registers during mma/epilogue.
// ---------------------------------------------------------------------------
#define XOFF 9216
#define APPLY_SMEM (9216 + 17408)

__global__ void __launch_bounds__(256, 2) apply_kernel(const float* __restrict__ x,
                                                       const float* __restrict__ b_out,
                                                       const float* __restrict__ gain,
                                                       float* __restrict__ out) {
    extern __shared__ char smem[];
    const uint32_t sb = smem_u32(smem);
    const int tid = threadIdx.x, wid = tid >> 5, lane = tid & 31;
    const int b = blockIdx.y;
    const float* xb = x + (size_t)b * NCH * N_TOK;
    float* ob = out + (size_t)b * NCH * N_TOK;

    // build A: M as fp16, 64 rows x 64 cols, stride 72 halves
    {
        const float* Mb = g_M + b * 4096;
        __half* pa = reinterpret_cast<__half*>(smem);
        for (int e = tid; e < 4096; e += 256) {
            int o = e >> 6, c = e & 63;
            pa[o * 72 + c] = __float2half(Mb[e]);
        }
    }

    const int row = lane >> 2;
    float bb[4][2], gg[4][2];
#pragma unroll
    for (int m = 0; m < 4; m++)
#pragma unroll
        for (int rh = 0; rh < 2; rh++) {
            int o = 16 * m + row + 8 * rh;
            bb[m][rh] = b_out[o];
            gg[m][rh] = gain[o];
        }

    const int tw = 16 * wid;
    const uint32_t xTB = sb + XOFF +
        ((lane & 7) + ((lane >> 4) << 3)) * 272 + (tw + ((lane >> 3) & 1) * 8) * 2;
    const uint32_t aBa = sb + (lane & 15) * 144 + ((lane >> 4) & 1) * 16;

    // prefetch first tile
    float4 v[8];
    int tile = blockIdx.x;
#pragma unroll
    for (int j = 0; j < 4; j++) {
        int idx = j * 256 + tid;
        int c = idx >> 4, t8 = (idx & 15) << 3;
        const float* p = xb + (size_t)c * N_TOK + tile * 128 + t8;
        v[2 * j]     = *reinterpret_cast<const float4*>(p);
        v[2 * j + 1] = *reinterpret_cast<const float4*>(p + 4);
    }

    for (; tile < N_TOK / 128; tile += gridDim.x) {
        __syncthreads();
        // convert + store prefetched tile (single fp16, one STS.128 per 8 tok)
#pragma unroll
        for (int j = 0; j < 4; j++) {
            int idx = j * 256 + tid;
            int c = idx >> 4, t8 = (idx & 15) << 3;
            float4 v0 = v[2 * j], v1 = v[2 * j + 1];
            uint4 hw;
            hw.x = cvt2h(v0.x, v0.y); hw.y = cvt2h(v0.z, v0.w);
            hw.z = cvt2h(v1.x, v1.y); hw.w = cvt2h(v1.z, v1.w);
            *reinterpret_cast<uint4*>(smem + XOFF + c * 272 + t8 * 2) = hw;
        }
        __syncthreads();

        // prefetch next tile's raw fp32 (overlaps with mma + epilogue)
        const int ntile = tile + gridDim.x;
        if (ntile < N_TOK / 128) {
#pragma unroll
            for (int j = 0; j < 4; j++) {
                int idx = j * 256 + tid;
                int c = idx >> 4, t8 = (idx & 15) << 3;
                const float* p = xb + (size_t)c * N_TOK + ntile * 128 + t8;
                v[2 * j]     = *reinterpret_cast<const float4*>(p);
                v[2 * j + 1] = *reinterpret_cast<const float4*>(p + 4);
            }
        }

        float d[4][2][4];
#pragma unroll
        for (int m = 0; m < 4; m++)
#pragma unroll
            for (int nn = 0; nn < 2; nn++)
#pragma unroll
                for (int r = 0; r < 4; r++) d[m][nn][r] = 0.0f;

#pragma unroll
        for (int kp = 0; kp < 4; kp++) {
            uint32_t bh[4];
            ldsm4t(bh, xTB + kp * 4352);
#pragma unroll
            for (int m = 0; m < 4; m++) {
                uint32_t af[4];
                ldsm4(af, aBa + m * 2304 + kp * 32);
                mma16816(d[m][0], af, bh[0], bh[2]);
                mma16816(d[m][1], af, bh[1], bh[3]);
            }
        }

        // epilogue: bias, per-token stats, normalize, store
        float yy[4][2][4];
        float s[2][2] = {{0.f, 0.f}, {0.f, 0.f}};
        float qq[2][2] = {{0.f, 0.f}, {0.f, 0.f}};
#pragma unroll
        for (int m = 0; m < 4; m++)
#pragma unroll
            for (int nn = 0; nn < 2; nn++)
#pragma unroll
                for (int r = 0; r < 4; r++) {
                    float vv = d[m][nn][r] + bb[m][r >> 1];
                    yy[m][nn][r] = vv;
                    s[nn][r & 1] += vv;
                    qq[nn][r & 1] += vv * vv;
                }
#pragma unroll
        for (int mask = 4; mask < 32; mask <<= 1)
#pragma unroll
            for (int nn = 0; nn < 2; nn++)
#pragma unroll
                for (int p = 0; p < 2; p++) {
                    s[nn][p]  += __shfl_xor_sync(0xffffffffu, s[nn][p], mask);
                    qq[nn][p] += __shfl_xor_sync(0xffffffffu, qq[nn][p], mask);
                }
        float mean[2][2], istd[2][2];
#pragma unroll
        for (int nn = 0; nn < 2; nn++)
#pragma unroll
            for (int p = 0; p < 2; p++) {
                float mu = s[nn][p] * (1.0f / 64.0f);
                mean[nn][p] = mu;
                istd[nn][p] = rsqrtf(qq[nn][p] * (1.0f / 64.0f) - mu * mu + 1e-5f);
            }

        float* obp = ob + (size_t)tile * 128;
#pragma unroll
        for (int m = 0; m < 4; m++)
#pragma unroll
            for (int nn = 0; nn < 2; nn++) {
                const int o  = 16 * m + row;
                const int tt = tw + 8 * nn + 2 * (lane & 3);
                stcs2(obp + (size_t)o * N_TOK + tt,
                      (yy[m][nn][0] - mean[nn][0]) * istd[nn][0] * gg[m][0],
                      (yy[m][nn][1] - mean[nn][1]) * istd[nn][1] * gg[m][0]);
                stcs2(obp + (size_t)(o + 8) * N_TOK + tt,
                      (yy[m][nn][2] - mean[nn][0]) * istd[nn][0] * gg[m][1],
                      (yy[m][nn][3] - mean[nn][1]) * istd[nn][1] * gg[m][1]);
            }
    }
}

// ---------------------------------------------------------------------------
extern "C" void kernel_launch(void* const* d_in, const int* in_sizes, int n_in,
                              void* d_out, int out_size) {
    const float* x     = (const float*)d_in[0];
    const float* w_qkv = (const float*)d_in[1];
    const float* w_out = (const float*)d_in[2];
    const float* b_out = (const float*)d_in[3];
    const float* g     = (const float*)d_in[4];
    float* out = (float*)d_out;

    cudaFuncSetAttribute(apply_kernel, cudaFuncAttributeMaxDynamicSharedMemorySize, APPLY_SMEM);

    zero_kernel<<<32, 256>>>();
    gram_kernel<<<dim3(148, 2), 256, GRAM_SMEM>>>(x);
    combine_kernel<<<dim3(4, 2), 256>>>(w_qkv, w_out);
    apply_kernel<<<dim3(296, 2), 256, APPLY_SMEM>>>(x, b_out, g, out);
}

// round 10
// speedup vs baseline: 2.6090x; 1.0484x over previous
#include <cuda_runtime.h>
#include <cuda_fp16.h>
#include <cstdint>

#define N_TOK 262144
#define NCH   64

__device__ float g_S[2 * 4096];
__device__ float g_M[2 * 4096];   // M: [o][c], c contiguous

// ---------------------------------------------------------------------------
static __device__ __forceinline__ uint32_t smem_u32(const void* p) {
    uint32_t a;
    asm("{ .reg .u64 t; cvta.to.shared.u64 t, %1; cvt.u32.u64 %0, t; }" : "=r"(a) : "l"(p));
    return a;
}
static __device__ __forceinline__ void ldsm4(uint32_t (&r)[4], uint32_t a) {
    asm volatile("ldmatrix.sync.aligned.m8n8.x4.shared.b16 {%0,%1,%2,%3}, [%4];"
                 : "=r"(r[0]), "=r"(r[1]), "=r"(r[2]), "=r"(r[3]) : "r"(a));
}
static __device__ __forceinline__ void ldsm4t(uint32_t (&r)[4], uint32_t a) {
    asm volatile("ldmatrix.sync.aligned.m8n8.x4.trans.shared.b16 {%0,%1,%2,%3}, [%4];"
                 : "=r"(r[0]), "=r"(r[1]), "=r"(r[2]), "=r"(r[3]) : "r"(a));
}
static __device__ __forceinline__ void mma16816(float (&d)[4], const uint32_t (&a)[4],
                                                uint32_t b0, uint32_t b1) {
    asm volatile("mma.sync.aligned.m16n8k16.row.col.f32.f16.f16.f32 "
                 "{%0,%1,%2,%3},{%4,%5,%6,%7},{%8,%9},{%0,%1,%2,%3};"
                 : "+f"(d[0]), "+f"(d[1]), "+f"(d[2]), "+f"(d[3])
                 : "r"(a[0]), "r"(a[1]), "r"(a[2]), "r"(a[3]), "r"(b0), "r"(b1));
}
static __device__ __forceinline__ uint32_t cvt2h(float lo, float hi) {
    uint32_t d;
    asm("cvt.rn.f16x2.f32 %0,%1,%2;" : "=r"(d) : "f"(hi), "f"(lo));
    return d;
}
static __device__ __forceinline__ void stcs2(float* p, float a, float b) {
    asm volatile("st.global.cs.v2.f32 [%0], {%1,%2};" :: "l"(p), "f"(a), "f"(b) : "memory");
}
static __device__ __forceinline__ void cp16(uint32_t dst, const void* src) {
    asm volatile("cp.async.cg.shared.global [%0], [%1], 16;" :: "r"(dst), "l"(src));
}
#define CP_COMMIT() asm volatile("cp.async.commit_group;" ::: "memory")
#define CP_WAIT1()  asm volatile("cp.async.wait_group 1;" ::: "memory")
#define CP_WAIT0()  asm volatile("cp.async.wait_group 0;" ::: "memory")

// ---------------------------------------------------------------------------
__global__ void zero_kernel() {
    int i = blockIdx.x * 256 + threadIdx.x;
    if (i < 2 * 4096) { g_S[i] = 0.0f; g_M[i] = 0.0f; }
}

// ---------------------------------------------------------------------------
// Pass A (fp16, cp.async 2-deep): S = X16·X16^T. 128-token tiles.
// raw fp32 tile staged by cp.async (2 stages x 32KB); convert LDS->cvt->STS
// into f16 tile [64 ch][128 tok] stride 272B. Warp = (mw stripe, kh tok-half).
// D[16][64] in regs across all tiles; epilogue combines 2 kh regions + atomic.
// smem: f16 @0 (17408), raw @17408 (2x32768) = 82944 B.
// ---------------------------------------------------------------------------
#define G_F16 0
#define G_RAW 17408
#define GRAM_SMEM (17408 + 2 * 32768)

__global__ void __launch_bounds__(256, 2) gram_kernel(const float* __restrict__ x) {
    extern __shared__ char smem[];
    const uint32_t sb = smem_u32(smem);
    const int tid = threadIdx.x, wid = tid >> 5, lane = tid & 31;
    const int b = blockIdx.y;
    const float* xb = x + (size_t)b * NCH * N_TOK;
    const int mw = wid & 3, kh = wid >> 2;
    const int NT = N_TOK / 128, S = gridDim.x;

    float d[8][4];
#pragma unroll
    for (int nn = 0; nn < 8; nn++)
#pragma unroll
        for (int r = 0; r < 4; r++) d[nn][r] = 0.0f;

    const uint32_t aAddr = sb + G_F16 + (16 * mw + (lane & 15)) * 272 + ((lane >> 4) & 1) * 16 + kh * 128;
    const uint32_t bBase = sb + G_F16 + (lane & 15) * 272 + ((lane >> 4) & 1) * 16 + kh * 128;

    // prologue: fill both stages
#pragma unroll
    for (int s2 = 0; s2 < 2; s2++) {
        int tt = blockIdx.x + s2 * S;
        if (tt < NT) {
#pragma unroll
            for (int k = 0; k < 8; k++) {
                int idx = k * 256 + tid;
                int c = idx >> 5, t4 = (idx & 31) << 2;
                cp16(sb + G_RAW + s2 * 32768 + c * 512 + t4 * 4,
                     xb + (size_t)c * N_TOK + tt * 128 + t4);
            }
        }
        CP_COMMIT();
    }

    int stage = 0;
    for (int tile = blockIdx.x; tile < NT; tile += S, stage ^= 1) {
        CP_WAIT1();
        __syncthreads();
        // convert raw[stage] -> f16 tile
        const char* rp = smem + G_RAW + stage * 32768;
#pragma unroll
        for (int j = 0; j < 4; j++) {
            int idx = j * 256 + tid;
            int c = idx >> 4, t8 = (idx & 15) << 3;
            float4 v0 = *reinterpret_cast<const float4*>(rp + c * 512 + t8 * 4);
            float4 v1 = *reinterpret_cast<const float4*>(rp + c * 512 + t8 * 4 + 16);
            uint4 hw;
            hw.x = cvt2h(v0.x, v0.y); hw.y = cvt2h(v0.z, v0.w);
            hw.z = cvt2h(v1.x, v1.y); hw.w = cvt2h(v1.z, v1.w);
            *reinterpret_cast<uint4*>(smem + G_F16 + c * 272 + t8 * 2) = hw;
        }
        __syncthreads();
        // prefetch tile+2S into raw[stage]
        {
            int pf = tile + 2 * S;
            if (pf < NT) {
#pragma unroll
                for (int k = 0; k < 8; k++) {
                    int idx = k * 256 + tid;
                    int c = idx >> 5, t4 = (idx & 31) << 2;
                    cp16(sb + G_RAW + stage * 32768 + c * 512 + t4 * 4,
                         xb + (size_t)c * N_TOK + pf * 128 + t4);
                }
            }
            CP_COMMIT();
        }
        // mma: 4 k-steps over this warp's 64-token half
#pragma unroll
        for (int k = 0; k < 4; k++) {
            uint32_t af[4];
            ldsm4(af, aAddr + k * 32);
#pragma unroll
            for (int nn2 = 0; nn2 < 4; nn2++) {
                uint32_t bf[4];
                ldsm4(bf, bBase + nn2 * (16 * 272) + k * 32);
                mma16816(d[2 * nn2],     af, bf[0], bf[2]);
                mma16816(d[2 * nn2 + 1], af, bf[1], bf[3]);
            }
        }
    }

    CP_WAIT0();
    __syncthreads();
    // stage D to smem region kh (float[64][68] each), in raw area
    float* sf = reinterpret_cast<float*>(smem + G_RAW) + kh * 4352;
    const int row0 = 16 * mw + (lane >> 2);
    const int col0 = 2 * (lane & 3);
#pragma unroll
    for (int nn = 0; nn < 8; nn++) {
        sf[row0 * 68 + 8 * nn + col0]           = d[nn][0];
        sf[row0 * 68 + 8 * nn + col0 + 1]       = d[nn][1];
        sf[(row0 + 8) * 68 + 8 * nn + col0]     = d[nn][2];
        sf[(row0 + 8) * 68 + 8 * nn + col0 + 1] = d[nn][3];
    }
    __syncthreads();

    float* Sb = g_S + b * 4096;
    float* sf0 = reinterpret_cast<float*>(smem + G_RAW);
#pragma unroll
    for (int kk = 0; kk < 16; kk++) {
        int e = kk * 256 + tid;
        int i = e >> 6, j2 = e & 63;
        atomicAdd(&Sb[e], sf0[i * 68 + j2] + sf0[4352 + i * 68 + j2]);
    }
}

// ---------------------------------------------------------------------------
// Pass B: fold weights into M[o][c]. One block per (head, batch).
// ---------------------------------------------------------------------------
__global__ void __launch_bounds__(256) combine_kernel(const float* __restrict__ w_qkv,
                                                      const float* __restrict__ w_out) {
    __shared__ float sS[4096];
    __shared__ float sA[2048];
    __shared__ float sC[1024];
    __shared__ float sP[2048];
    const int b = blockIdx.y, h = blockIdx.x;
    const int tid = threadIdx.x;

    const float* Sb = g_S + b * 4096;
    for (int k = tid; k < 4096; k += 256) sS[k] = Sb[k];
    __syncthreads();

    const float* Wq = w_qkv + (h * 32) * 64;
    const float* Wk = w_qkv + (128 + h * 32) * 64;
    const float* Wv = w_qkv + (256 + h * 32) * 64;

    for (int e = tid; e < 2048; e += 256) {
        int ii = e >> 6, c = e & 63;
        float s = 0.0f;
        for (int c2 = 0; c2 < 64; c2++) s += Wk[ii * 64 + c2] * sS[c2 * 64 + c];
        sA[e] = s;
    }
    __syncthreads();

    const float coef = 0.17677669529663688f / 4096.0f;
    for (int e = tid; e < 1024; e += 256) {
        int ii = e >> 5, jj = e & 31;
        float s = 0.0f;
        for (int c = 0; c < 64; c++) s += sA[ii * 64 + c] * Wv[jj * 64 + c];
        sC[e] = s * coef;
    }
    __syncthreads();

    for (int e = tid; e < 2048; e += 256) {
        int jj = e >> 6, c = e & 63;
        float s = 0.0f;
        for (int ii = 0; ii < 32; ii++) s += sC[ii * 32 + jj] * Wq[ii * 64 + c];
        sP[e] = s;
    }
    __syncthreads();

    float* Mb = g_M + b * 4096;
    for (int e = tid; e < 4096; e += 256) {
        int o = e >> 6, c = e & 63;
        float s = 0.0f;
        for (int jj = 0; jj < 32; jj++) s += w_out[o * 128 + h * 32 + jj] * sP[jj * 64 + c];
        atomicAdd(&Mb[e], s);
    }
}

// ---------------------------------------------------------------------------
// Pass C (fp16, cp.async 2-deep): y = M16 · x16, channel LayerNorm * gain.
// A = M f16 [64 o][64 c] stride 144B. X tile f16 [64 ch][128 tok] stride 272B
// (B via ldmatrix.trans). raw fp32 staged by cp.async (2 x 32KB).
// Warp owns 16 tokens; LN 3-shfl butterfly; STG.64 .cs streaming stores.
// smem: M @0 (9216), f16 X @9216 (17408), raw @26624 (2x32768) = 92160 B.
// ---------------------------------------------------------------------------
#define A_M   0
#define A_F16 9216
#define A_RAW 26624
#define APPLY_SMEM (26624 + 2 * 32768)

__global__ void __launch_bounds__(256, 2) apply_kernel(const float* __restrict__ x,
                                                       const float* __restrict__ b_out,
                                                       const float* __restrict__ gain,
                                                       float* __restrict__ out) {
    extern __shared__ char smem[];
    const uint32_t sb = smem_u32(smem);
    const int tid = threadIdx.x, wid = tid >> 5, lane = tid & 31;
    const int b = blockIdx.y;
    const float* xb = x + (size_t)b * NCH * N_TOK;
    float* ob = out + (size_t)b * NCH * N_TOK;
    const int NT = N_TOK / 128, S = gridDim.x;

    // build A: M as fp16, 64 rows x 64 cols, stride 72 halves
    {
        const float* Mb = g_M + b * 4096;
        __half* pa = reinterpret_cast<__half*>(smem);
        for (int e = tid; e < 4096; e += 256) {
            int o = e >> 6, c = e & 63;
            pa[o * 72 + c] = __float2half(Mb[e]);
        }
    }

    const int row = lane >> 2;
    float bb[4][2], gg[4][2];
#pragma unroll
    for (int m = 0; m < 4; m++)
#pragma unroll
        for (int rh = 0; rh < 2; rh++) {
            int o = 16 * m + row + 8 * rh;
            bb[m][rh] = b_out[o];
            gg[m][rh] = gain[o];
        }

    const int tw = 16 * wid;
    const uint32_t xTB = sb + A_F16 +
        ((lane & 7) + ((lane >> 4) << 3)) * 272 + (tw + ((lane >> 3) & 1) * 8) * 2;
    const uint32_t aBa = sb + A_M + (lane & 15) * 144 + ((lane >> 4) & 1) * 16;

    // prologue: fill both stages
#pragma unroll
    for (int s2 = 0; s2 < 2; s2++) {
        int tt = blockIdx.x + s2 * S;
        if (tt < NT) {
#pragma unroll
            for (int k = 0; k < 8; k++) {
                int idx = k * 256 + tid;
                int c = idx >> 5, t4 = (idx & 31) << 2;
                cp16(sb + A_RAW + s2 * 32768 + c * 512 + t4 * 4,
                     xb + (size_t)c * N_TOK + tt * 128 + t4);
            }
        }
        CP_COMMIT();
    }

    int stage = 0;
    for (int tile = blockIdx.x; tile < NT; tile += S, stage ^= 1) {
        CP_WAIT1();
        __syncthreads();
        // convert raw[stage] -> f16 X tile
        const char* rp = smem + A_RAW + stage * 32768;
#pragma unroll
        for (int j = 0; j < 4; j++) {
            int idx = j * 256 + tid;
            int c = idx >> 4, t8 = (idx & 15) << 3;
            float4 v0 = *reinterpret_cast<const float4*>(rp + c * 512 + t8 * 4);
            float4 v1 = *reinterpret_cast<const float4*>(rp + c * 512 + t8 * 4 + 16);
            uint4 hw;
            hw.x = cvt2h(v0.x, v0.y); hw.y = cvt2h(v0.z, v0.w);
            hw.z = cvt2h(v1.x, v1.y); hw.w = cvt2h(v1.z, v1.w);
            *reinterpret_cast<uint4*>(smem + A_F16 + c * 272 + t8 * 2) = hw;
        }
        __syncthreads();
        // prefetch tile+2S into raw[stage]
        {
            int pf = tile + 2 * S;
            if (pf < NT) {
#pragma unroll
                for (int k = 0; k < 8; k++) {
                    int idx = k * 256 + tid;
                    int c = idx >> 5, t4 = (idx & 31) << 2;
                    cp16(sb + A_RAW + stage * 32768 + c * 512 + t4 * 4,
                         xb + (size_t)c * N_TOK + pf * 128 + t4);
                }
            }
            CP_COMMIT();
        }

        float d[4][2][4];
#pragma unroll
        for (int m = 0; m < 4; m++)
#pragma unroll
            for (int nn = 0; nn < 2; nn++)
#pragma unroll
                for (int r = 0; r < 4; r++) d[m][nn][r] = 0.0f;

#pragma unroll
        for (int kp = 0; kp < 4; kp++) {
            uint32_t bh[4];
            ldsm4t(bh, xTB + kp * 4352);
#pragma unroll
            for (int m = 0; m < 4; m++) {
                uint32_t af[4];
                ldsm4(af, aBa + m * 2304 + kp * 32);
                mma16816(d[m][0], af, bh[0], bh[2]);
                mma16816(d[m][1], af, bh[1], bh[3]);
            }
        }

        // epilogue: bias, per-token stats, normalize, store
        float yy[4][2][4];
        float s[2][2] = {{0.f, 0.f}, {0.f, 0.f}};
        float qq[2][2] = {{0.f, 0.f}, {0.f, 0.f}};
#pragma unroll
        for (int m = 0; m < 4; m++)
#pragma unroll
            for (int nn = 0; nn < 2; nn++)
#pragma unroll
                for (int r = 0; r < 4; r++) {
                    float vv = d[m][nn][r] + bb[m][r >> 1];
                    yy[m][nn][r] = vv;
                    s[nn][r & 1] += vv;
                    qq[nn][r & 1] += vv * vv;
                }
#pragma unroll
        for (int mask = 4; mask < 32; mask <<= 1)
#pragma unroll
            for (int nn = 0; nn < 2; nn++)
#pragma unroll
                for (int p = 0; p < 2; p++) {
                    s[nn][p]  += __shfl_xor_sync(0xffffffffu, s[nn][p], mask);
                    qq[nn][p] += __shfl_xor_sync(0xffffffffu, qq[nn][p], mask);
                }
        float mean[2][2], istd[2][2];
#pragma unroll
        for (int nn = 0; nn < 2; nn++)
#pragma unroll
            for (int p = 0; p < 2; p++) {
                float mu = s[nn][p] * (1.0f / 64.0f);
                mean[nn][p] = mu;
                istd[nn][p] = rsqrtf(qq[nn][p] * (1.0f / 64.0f) - mu * mu + 1e-5f);
            }

        float* obp = ob + (size_t)tile * 128;
#pragma unroll
        for (int m = 0; m < 4; m++)
#pragma unroll
            for (int nn = 0; nn < 2; nn++) {
                const int o  = 16 * m + row;
                const int tt = tw + 8 * nn + 2 * (lane & 3);
                stcs2(obp + (size_t)o * N_TOK + tt,
                      (yy[m][nn][0] - mean[nn][0]) * istd[nn][0] * gg[m][0],
                      (yy[m][nn][1] - mean[nn][1]) * istd[nn][1] * gg[m][0]);
                stcs2(obp + (size_t)(o + 8) * N_TOK + tt,
                      (yy[m][nn][2] - mean[nn][0]) * istd[nn][0] * gg[m][1],
                      (yy[m][nn][3] - mean[nn][1]) * istd[nn][1] * gg[m][1]);
            }
    }
}

// ---------------------------------------------------------------------------
extern "C" void kernel_launch(void* const* d_in, const int* in_sizes, int n_in,
                              void* d_out, int out_size) {
    const float* x     = (const float*)d_in[0];
    const float* w_qkv = (const float*)d_in[1];
    const float* w_out = (const float*)d_in[2];
    const float* b_out = (const float*)d_in[3];
    const float* g     = (const float*)d_in[4];
    float* out = (float*)d_out;

    cudaFuncSetAttribute(gram_kernel,  cudaFuncAttributeMaxDynamicSharedMemorySize, GRAM_SMEM);
    cudaFuncSetAttribute(apply_kernel, cudaFuncAttributeMaxDynamicSharedMemorySize, APPLY_SMEM);

    zero_kernel<<<32, 256>>>();
    gram_kernel<<<dim3(148, 2), 256, GRAM_SMEM>>>(x);
    combine_kernel<<<dim3(4, 2), 256>>>(w_qkv, w_out);
    apply_kernel<<<dim3(148, 2), 256, APPLY_SMEM>>>(x, b_out, g, out);
}